// round 1
// baseline (speedup 1.0000x reference)
#include <cuda_runtime.h>
#include <math.h>

#define T 4096
#define H 1024
#define F 512
#define E 16
#define K 4
#define S (T*K)

#define BM 64
#define BN 64
#define BK 32

// ---- scratch (device globals; no runtime allocation) ----
__device__ int   g_topi[S];
__device__ float g_topw[S];
__device__ int   g_counts[E];
__device__ int   g_off[E + 1];
__device__ int   g_cursor[E];
__device__ int   g_slot_token[S];
__device__ float g_slot_w[S];
__device__ int   g_token_slot[S];
__device__ float g_h[(size_t)S * F];   // 32 MB: SwiGLU activations per slot
__device__ float g_y[(size_t)S * H];   // 64 MB: per-slot weighted expert output

// ---------------------------------------------------------------------------
// 1. zero histograms (graph is replayed; every launch must rebuild state)
// ---------------------------------------------------------------------------
__global__ void init_kernel() {
    int i = threadIdx.x;
    if (i < E) g_counts[i] = 0;
}

// ---------------------------------------------------------------------------
// 2. router: one warp per token
// ---------------------------------------------------------------------------
__global__ void router_kernel(const float* __restrict__ x,
                              const float* __restrict__ gw,
                              const float* __restrict__ bias) {
    int warp = (blockIdx.x * blockDim.x + threadIdx.x) >> 5;
    int lane = threadIdx.x & 31;
    if (warp >= T) return;

    const float* xr = x + (size_t)warp * H;
    float acc[E];
#pragma unroll
    for (int e = 0; e < E; e++) acc[e] = 0.f;

    for (int h = lane; h < H; h += 32) {
        float xv = xr[h];
#pragma unroll
        for (int e = 0; e < E; e++)
            acc[e] = fmaf(xv, __ldg(&gw[e * H + h]), acc[e]);
    }
#pragma unroll
    for (int o = 16; o > 0; o >>= 1) {
#pragma unroll
        for (int e = 0; e < E; e++)
            acc[e] += __shfl_xor_sync(0xffffffffu, acc[e], o);
    }

    if (lane == 0) {
        float sc[E], sel[E];
#pragma unroll
        for (int e = 0; e < E; e++) {
            sc[e]  = 1.f / (1.f + expf(-acc[e]));  // sigmoid score
            sel[e] = sc[e] + bias[e];              // bias-corrected for selection
        }
        bool used[E];
#pragma unroll
        for (int e = 0; e < E; e++) used[e] = false;

        int   idx[K];
        float w[K];
        float sum = 0.f;
#pragma unroll
        for (int k = 0; k < K; k++) {
            float best = -1e30f; int bi = 0;
            for (int e = 0; e < E; e++)
                if (!used[e] && sel[e] > best) { best = sel[e]; bi = e; }
            used[bi] = true;
            idx[k] = bi;
            w[k]   = sc[bi];   // combine uses RAW sigmoid scores
            sum   += sc[bi];
        }
        float inv = 1.f / sum;
#pragma unroll
        for (int k = 0; k < K; k++) {
            g_topi[warp * K + k] = idx[k];
            g_topw[warp * K + k] = w[k] * inv;
            atomicAdd(&g_counts[idx[k]], 1);
        }
    }
}

// ---------------------------------------------------------------------------
// 3. scan offsets (E=16, trivial)
// ---------------------------------------------------------------------------
__global__ void scan_kernel() {
    int o = 0;
    g_off[0] = 0;
    for (int e = 0; e < E; e++) {
        o += g_counts[e];
        g_off[e + 1] = o;
        g_cursor[e]  = g_off[e];
    }
}

// ---------------------------------------------------------------------------
// 4. scatter: compact (token,k) into per-expert slot lists
// ---------------------------------------------------------------------------
__global__ void scatter_kernel() {
    int i = blockIdx.x * blockDim.x + threadIdx.x;
    if (i >= S) return;
    int e   = g_topi[i];
    int pos = atomicAdd(&g_cursor[e], 1);
    g_slot_token[pos] = i >> 2;          // token id
    g_slot_w[pos]     = g_topw[i];
    g_token_slot[i]   = pos;             // token -> its K slots (for combine)
}

// ---------------------------------------------------------------------------
// 5. grouped GEMM 1: h = silu(x@W1^T) * (x@W3^T), gathered rows
// ---------------------------------------------------------------------------
__global__ __launch_bounds__(256) void gemm1_kernel(
        const float* __restrict__ x,
        const float* __restrict__ w1,
        const float* __restrict__ w3) {
    int e     = blockIdx.x;
    int off   = g_off[e];
    int count = g_off[e + 1] - off;
    int m0    = blockIdx.y * BM;
    if (m0 >= count) return;
    int n0 = blockIdx.z * BN;

    __shared__ float xs [BM][BK + 1];
    __shared__ float w1s[BN][BK + 1];
    __shared__ float w3s[BN][BK + 1];
    __shared__ int   toks[BM];

    int tid = threadIdx.x;
    if (tid < BM) {
        int r = m0 + tid;
        toks[tid] = g_slot_token[off + min(r, count - 1)];
    }
    __syncthreads();

    const float* w1e = w1 + ((size_t)e * F + n0) * H;
    const float* w3e = w3 + ((size_t)e * F + n0) * H;

    int tx = tid & 15, ty = tid >> 4;
    float a1[4][4] = {}, a3[4][4] = {};

    for (int k0 = 0; k0 < H; k0 += BK) {
#pragma unroll
        for (int l = 0; l < (BM * BK) / 256; l++) {
            int idx = tid + l * 256;
            int m = idx >> 5, k = idx & 31;
            xs [m][k] = x  [(size_t)toks[m] * H + k0 + k];
            w1s[m][k] = w1e[(size_t)m       * H + k0 + k];
            w3s[m][k] = w3e[(size_t)m       * H + k0 + k];
        }
        __syncthreads();
#pragma unroll
        for (int kk = 0; kk < BK; kk++) {
            float av[4], b1[4], b3[4];
#pragma unroll
            for (int i = 0; i < 4; i++) av[i] = xs[ty * 4 + i][kk];
#pragma unroll
            for (int j = 0; j < 4; j++) {
                b1[j] = w1s[tx * 4 + j][kk];
                b3[j] = w3s[tx * 4 + j][kk];
            }
#pragma unroll
            for (int i = 0; i < 4; i++)
#pragma unroll
                for (int j = 0; j < 4; j++) {
                    a1[i][j] = fmaf(av[i], b1[j], a1[i][j]);
                    a3[i][j] = fmaf(av[i], b3[j], a3[i][j]);
                }
        }
        __syncthreads();
    }

#pragma unroll
    for (int i = 0; i < 4; i++) {
        int m = m0 + ty * 4 + i;
        if (m >= count) continue;
        size_t row = (size_t)(off + m) * F + n0;
#pragma unroll
        for (int j = 0; j < 4; j++) {
            float g = a1[i][j], u = a3[i][j];
            g_h[row + tx * 4 + j] = (g / (1.f + expf(-g))) * u;  // silu(g)*u
        }
    }
}

// ---------------------------------------------------------------------------
// 6. grouped GEMM 2: y = c * (h @ W2^T)
// ---------------------------------------------------------------------------
__global__ __launch_bounds__(256) void gemm2_kernel(const float* __restrict__ w2) {
    int e     = blockIdx.x;
    int off   = g_off[e];
    int count = g_off[e + 1] - off;
    int m0    = blockIdx.y * BM;
    if (m0 >= count) return;
    int n0 = blockIdx.z * BN;

    __shared__ float hs[BM][BK + 1];
    __shared__ float ws[BN][BK + 1];
    __shared__ int   rows[BM];
    __shared__ float wts[BM];

    int tid = threadIdx.x;
    if (tid < BM) {
        int r  = m0 + tid;
        int cr = min(r, count - 1);
        rows[tid] = off + cr;
        wts[tid]  = g_slot_w[off + cr];
    }
    __syncthreads();

    const float* w2e = w2 + ((size_t)e * H + n0) * F;
    int tx = tid & 15, ty = tid >> 4;
    float acc[4][4] = {};

    for (int k0 = 0; k0 < F; k0 += BK) {
#pragma unroll
        for (int l = 0; l < (BM * BK) / 256; l++) {
            int idx = tid + l * 256;
            int m = idx >> 5, k = idx & 31;
            hs[m][k] = g_h[(size_t)rows[m] * F + k0 + k];
            ws[m][k] = w2e[(size_t)m      * F + k0 + k];
        }
        __syncthreads();
#pragma unroll
        for (int kk = 0; kk < BK; kk++) {
            float av[4], bv[4];
#pragma unroll
            for (int i = 0; i < 4; i++) av[i] = hs[ty * 4 + i][kk];
#pragma unroll
            for (int j = 0; j < 4; j++) bv[j] = ws[tx * 4 + j][kk];
#pragma unroll
            for (int i = 0; i < 4; i++)
#pragma unroll
                for (int j = 0; j < 4; j++)
                    acc[i][j] = fmaf(av[i], bv[j], acc[i][j]);
        }
        __syncthreads();
    }

#pragma unroll
    for (int i = 0; i < 4; i++) {
        int m = m0 + ty * 4 + i;
        if (m >= count) continue;
        float c = wts[ty * 4 + i];
        size_t row = (size_t)(off + m) * H + n0;
#pragma unroll
        for (int j = 0; j < 4; j++)
            g_y[row + tx * 4 + j] = c * acc[i][j];
    }
}

// ---------------------------------------------------------------------------
// 7. combine: out[t] = sum of the token's K slot rows (deterministic order)
// ---------------------------------------------------------------------------
__global__ void combine_kernel(float* __restrict__ out) {
    int t = blockIdx.x;
    int s0 = g_token_slot[t * K + 0];
    int s1 = g_token_slot[t * K + 1];
    int s2 = g_token_slot[t * K + 2];
    int s3 = g_token_slot[t * K + 3];
    for (int h = threadIdx.x; h < H; h += blockDim.x) {
        out[(size_t)t * H + h] =
            g_y[(size_t)s0 * H + h] + g_y[(size_t)s1 * H + h] +
            g_y[(size_t)s2 * H + h] + g_y[(size_t)s3 * H + h];
    }
}

// ---------------------------------------------------------------------------
extern "C" void kernel_launch(void* const* d_in, const int* in_sizes, int n_in,
                              void* d_out, int out_size) {
    const float* x    = (const float*)d_in[0];
    const float* gw   = (const float*)d_in[1];
    const float* bias = (const float*)d_in[2];
    const float* w1   = (const float*)d_in[3];
    const float* w3   = (const float*)d_in[4];
    const float* w2   = (const float*)d_in[5];
    float* out = (float*)d_out;

    init_kernel<<<1, 32>>>();
    router_kernel<<<(T * 32 + 255) / 256, 256>>>(x, gw, bias);
    scan_kernel<<<1, 1>>>();
    scatter_kernel<<<(S + 255) / 256, 256>>>();

    dim3 g1(E, (T + BM - 1) / BM, F / BN);
    gemm1_kernel<<<g1, 256>>>(x, w1, w3);

    dim3 g2(E, (T + BM - 1) / BM, H / BN);
    gemm2_kernel<<<g2, 256>>>(w2);

    combine_kernel<<<T, 256>>>(out);
}

// round 4
// speedup vs baseline: 3.0564x; 3.0564x over previous
#include <cuda_runtime.h>
#include <cstdint>
#include <math.h>

#define T 4096
#define H 1024
#define F 512
#define E 16
#define K 4
#define S (T*K)

// ---------------- scratch (device globals; no runtime allocation) ----------
__device__ int    g_topi[S];
__device__ float  g_topw[S];
__device__ int    g_counts[E];
__device__ int    g_off[E + 1];
__device__ int    g_cursor[E];
__device__ int    g_slot_token[S];
__device__ float  g_slot_w[S];
__device__ int    g_token_slot[S];
__device__ float  g_h[(size_t)S * F];   // SwiGLU activations per slot (fp32)
__device__ float  g_y[(size_t)S * H];   // per-slot weighted expert output

// ---------------- helpers ---------------------------------------------------
// NOTE: tf32 cvt destination must be a .b32 register (ptxas rejects .f32 dst)
__device__ __forceinline__ float rna_tf32(float v) {
    uint32_t r;
    asm("cvt.rna.tf32.f32 %0, %1;" : "=r"(r) : "f"(v));
    return __uint_as_float(r);
}
__device__ __forceinline__ float4 rna4(float4 v) {
    v.x = rna_tf32(v.x); v.y = rna_tf32(v.y);
    v.z = rna_tf32(v.z); v.w = rna_tf32(v.w);
    return v;
}
// D += A*B, m16n8k8 tf32 (sm_80+; valid on base sm_100)
__device__ __forceinline__ void mma8(float* d, const uint32_t* a, const uint32_t* b) {
    asm volatile(
        "mma.sync.aligned.m16n8k8.row.col.f32.tf32.tf32.f32 "
        "{%0,%1,%2,%3}, {%4,%5,%6,%7}, {%8,%9}, {%0,%1,%2,%3};"
        : "+f"(d[0]), "+f"(d[1]), "+f"(d[2]), "+f"(d[3])
        : "r"(a[0]), "r"(a[1]), "r"(a[2]), "r"(a[3]), "r"(b[0]), "r"(b[1]));
}
__device__ __forceinline__ uint32_t fbits(float v) { return __float_as_uint(v); }

#define BM 64
#define BN 128
#define BK 16
#define LDP 20          // padded smem row stride (floats): conflict-free frags

// ---------------------------------------------------------------------------
// 1. init / 2. router (exact fp32) / 3. scan / 4. scatter
// ---------------------------------------------------------------------------
__global__ void init_kernel() {
    int i = threadIdx.x;
    if (i < E) g_counts[i] = 0;
}

__global__ void router_kernel(const float* __restrict__ x,
                              const float* __restrict__ gw,
                              const float* __restrict__ bias) {
    int warp = (blockIdx.x * blockDim.x + threadIdx.x) >> 5;
    int lane = threadIdx.x & 31;
    if (warp >= T) return;

    const float* xr = x + (size_t)warp * H;
    float acc[E];
#pragma unroll
    for (int e = 0; e < E; e++) acc[e] = 0.f;
    for (int h = lane; h < H; h += 32) {
        float xv = xr[h];
#pragma unroll
        for (int e = 0; e < E; e++)
            acc[e] = fmaf(xv, __ldg(&gw[e * H + h]), acc[e]);
    }
#pragma unroll
    for (int o = 16; o > 0; o >>= 1)
#pragma unroll
        for (int e = 0; e < E; e++)
            acc[e] += __shfl_xor_sync(0xffffffffu, acc[e], o);

    if (lane == 0) {
        float sc[E], sel[E];
#pragma unroll
        for (int e = 0; e < E; e++) {
            sc[e]  = 1.f / (1.f + expf(-acc[e]));
            sel[e] = sc[e] + bias[e];
        }
        bool used[E];
#pragma unroll
        for (int e = 0; e < E; e++) used[e] = false;
        float sum = 0.f;
        int   idx[K]; float w[K];
#pragma unroll
        for (int k = 0; k < K; k++) {
            float best = -1e30f; int bi = 0;
            for (int e = 0; e < E; e++)
                if (!used[e] && sel[e] > best) { best = sel[e]; bi = e; }
            used[bi] = true; idx[k] = bi; w[k] = sc[bi]; sum += sc[bi];
        }
        float inv = 1.f / sum;
#pragma unroll
        for (int k = 0; k < K; k++) {
            g_topi[warp * K + k] = idx[k];
            g_topw[warp * K + k] = w[k] * inv;
            atomicAdd(&g_counts[idx[k]], 1);
        }
    }
}

__global__ void scan_kernel() {
    int o = 0; g_off[0] = 0;
    for (int e = 0; e < E; e++) {
        o += g_counts[e];
        g_off[e + 1] = o;
        g_cursor[e]  = g_off[e];
    }
}

__global__ void scatter_kernel() {
    int i = blockIdx.x * blockDim.x + threadIdx.x;
    if (i >= S) return;
    int e   = g_topi[i];
    int pos = atomicAdd(&g_cursor[e], 1);
    g_slot_token[pos] = i >> 2;
    g_slot_w[pos]     = g_topw[i];
    g_token_slot[i]   = pos;
}

// ---------------------------------------------------------------------------
// 5. grouped GEMM 1 (mma.sync tf32): P1 = X@W1^T, P3 = X@W3^T, h=silu(P1)*P3
//    CTA tile 64(M) x 128(N) x 16(K-stage), 8 warps = 2(M) x 4(N), warp 32x32
// ---------------------------------------------------------------------------
__global__ __launch_bounds__(256) void gemm1_tc(
        const float* __restrict__ x,
        const float* __restrict__ w1,
        const float* __restrict__ w3) {
    int e     = blockIdx.z;
    int off   = g_off[e];
    int count = g_off[e + 1] - off;
    int m0    = blockIdx.x * BM;
    if (m0 >= count) return;
    int n0 = blockIdx.y * BN;

    extern __shared__ float sm[];
    float* xs  = sm;                       // [2][BM][LDP]
    float* w1s = sm + 2 * BM * LDP;        // [2][BN][LDP]
    float* w3s = w1s + 2 * BN * LDP;       // [2][BN][LDP]
    __shared__ int toks[BM];

    int tid  = threadIdx.x;
    int wid  = tid >> 5, lane = tid & 31;
    int q    = lane >> 2, tq = lane & 3;   // quad row / thread-in-quad
    int wM   = wid & 1, wN = wid >> 1;     // 2 x 4 warps

    if (tid < BM) toks[tid] = g_slot_token[off + min(m0 + tid, count - 1)];
    __syncthreads();

    const float* w1e = w1 + ((size_t)e * F + n0) * H;
    const float* w3e = w3 + ((size_t)e * F + n0) * H;

    // per-stage global fetch registers
    float4 rx, rw1[2], rw3[2];
    int xrow = tid >> 2, xc = (tid & 3) * 4;     // x: 64 rows x 16 -> 1 f4/thr
    int wrowA = tid >> 2, wcA = (tid & 3) * 4;   // w: 128 rows x 16 -> 2 f4/thr
    int wrowB = (tid + 256) >> 2, wcB = wcA;

    auto load_regs = [&](int k0) {
        rx     = *(const float4*)(x   + (size_t)toks[xrow] * H + k0 + xc);
        rw1[0] = *(const float4*)(w1e + (size_t)wrowA * H + k0 + wcA);
        rw1[1] = *(const float4*)(w1e + (size_t)wrowB * H + k0 + wcB);
        rw3[0] = *(const float4*)(w3e + (size_t)wrowA * H + k0 + wcA);
        rw3[1] = *(const float4*)(w3e + (size_t)wrowB * H + k0 + wcB);
    };
    auto store_smem = [&](int b) {
        *(float4*)(xs  + b * BM * LDP + xrow  * LDP + xc)  = rna4(rx);
        *(float4*)(w1s + b * BN * LDP + wrowA * LDP + wcA) = rna4(rw1[0]);
        *(float4*)(w1s + b * BN * LDP + wrowB * LDP + wcB) = rna4(rw1[1]);
        *(float4*)(w3s + b * BN * LDP + wrowA * LDP + wcA) = rna4(rw3[0]);
        *(float4*)(w3s + b * BN * LDP + wrowB * LDP + wcB) = rna4(rw3[1]);
    };

    float acc1[2][4][4] = {}, acc3[2][4][4] = {};

    load_regs(0);
    store_smem(0);
    __syncthreads();

    const int NK = H / BK;   // 64
    for (int kt = 0; kt < NK; kt++) {
        int b = kt & 1;
        if (kt + 1 < NK) load_regs((kt + 1) * BK);

        const float* xb  = xs  + b * BM * LDP;
        const float* w1b = w1s + b * BN * LDP;
        const float* w3b = w3s + b * BN * LDP;
#pragma unroll
        for (int ks = 0; ks < BK / 8; ks++) {
            int kc = ks * 8;
            uint32_t a[2][4];
#pragma unroll
            for (int mt = 0; mt < 2; mt++) {
                int r = wM * 32 + mt * 16 + q;
                a[mt][0] = fbits(xb[r * LDP + kc + tq]);
                a[mt][1] = fbits(xb[(r + 8) * LDP + kc + tq]);
                a[mt][2] = fbits(xb[r * LDP + kc + 4 + tq]);
                a[mt][3] = fbits(xb[(r + 8) * LDP + kc + 4 + tq]);
            }
            uint32_t b1[4][2], b3[4][2];
#pragma unroll
            for (int nt = 0; nt < 4; nt++) {
                int c = wN * 32 + nt * 8 + q;
                b1[nt][0] = fbits(w1b[c * LDP + kc + tq]);
                b1[nt][1] = fbits(w1b[c * LDP + kc + 4 + tq]);
                b3[nt][0] = fbits(w3b[c * LDP + kc + tq]);
                b3[nt][1] = fbits(w3b[c * LDP + kc + 4 + tq]);
            }
#pragma unroll
            for (int mt = 0; mt < 2; mt++)
#pragma unroll
                for (int nt = 0; nt < 4; nt++) {
                    mma8(acc1[mt][nt], a[mt], b1[nt]);
                    mma8(acc3[mt][nt], a[mt], b3[nt]);
                }
        }
        if (kt + 1 < NK) {
            store_smem(b ^ 1);
            __syncthreads();
        }
    }

    // epilogue: SwiGLU -> g_h (fp32; rounding happens at gemm2 staging)
#pragma unroll
    for (int mt = 0; mt < 2; mt++) {
#pragma unroll
        for (int half = 0; half < 2; half++) {
            int m = m0 + wM * 32 + mt * 16 + q + half * 8;
            if (m >= count) continue;
            float* hrow = g_h + (size_t)(off + m) * F + n0 + wN * 32;
#pragma unroll
            for (int nt = 0; nt < 4; nt++) {
                float g0 = acc1[mt][nt][half * 2 + 0];
                float g1 = acc1[mt][nt][half * 2 + 1];
                float u0 = acc3[mt][nt][half * 2 + 0];
                float u1 = acc3[mt][nt][half * 2 + 1];
                float2 o;
                o.x = (g0 / (1.f + expf(-g0))) * u0;
                o.y = (g1 / (1.f + expf(-g1))) * u1;
                *(float2*)(hrow + nt * 8 + 2 * tq) = o;
            }
        }
    }
}

// ---------------------------------------------------------------------------
// 6. grouped GEMM 2 (mma.sync tf32): y = c * (h @ W2^T)
// ---------------------------------------------------------------------------
__global__ __launch_bounds__(256) void gemm2_tc(const float* __restrict__ w2) {
    int e     = blockIdx.z;
    int off   = g_off[e];
    int count = g_off[e + 1] - off;
    int m0    = blockIdx.x * BM;
    if (m0 >= count) return;
    int n0 = blockIdx.y * BN;

    __shared__ float hs[2 * BM * LDP];
    __shared__ float ws[2 * BN * LDP];

    int tid  = threadIdx.x;
    int wid  = tid >> 5, lane = tid & 31;
    int q    = lane >> 2, tq = lane & 3;
    int wM   = wid & 1, wN = wid >> 1;

    const float* w2e = w2 + ((size_t)e * H + n0) * F;
    int cm1 = count - 1;

    float4 rh, rw[2];
    int hrow = tid >> 2, hc = (tid & 3) * 4;
    int wrowA = tid >> 2, wcA = (tid & 3) * 4;
    int wrowB = (tid + 256) >> 2, wcB = wcA;
    int arow = off + min(m0 + hrow, cm1);

    auto load_regs = [&](int k0) {
        rh    = *(const float4*)(g_h + (size_t)arow * F + k0 + hc);
        rw[0] = *(const float4*)(w2e + (size_t)wrowA * F + k0 + wcA);
        rw[1] = *(const float4*)(w2e + (size_t)wrowB * F + k0 + wcB);
    };
    auto store_smem = [&](int b) {
        *(float4*)(hs + b * BM * LDP + hrow  * LDP + hc)  = rna4(rh);
        *(float4*)(ws + b * BN * LDP + wrowA * LDP + wcA) = rna4(rw[0]);
        *(float4*)(ws + b * BN * LDP + wrowB * LDP + wcB) = rna4(rw[1]);
    };

    float acc[2][4][4] = {};

    load_regs(0);
    store_smem(0);
    __syncthreads();

    const int NK = F / BK;   // 32
    for (int kt = 0; kt < NK; kt++) {
        int b = kt & 1;
        if (kt + 1 < NK) load_regs((kt + 1) * BK);

        const float* hb = hs + b * BM * LDP;
        const float* wb = ws + b * BN * LDP;
#pragma unroll
        for (int ks = 0; ks < BK / 8; ks++) {
            int kc = ks * 8;
            uint32_t a[2][4];
#pragma unroll
            for (int mt = 0; mt < 2; mt++) {
                int r = wM * 32 + mt * 16 + q;
                a[mt][0] = fbits(hb[r * LDP + kc + tq]);
                a[mt][1] = fbits(hb[(r + 8) * LDP + kc + tq]);
                a[mt][2] = fbits(hb[r * LDP + kc + 4 + tq]);
                a[mt][3] = fbits(hb[(r + 8) * LDP + kc + 4 + tq]);
            }
            uint32_t bv[4][2];
#pragma unroll
            for (int nt = 0; nt < 4; nt++) {
                int c = wN * 32 + nt * 8 + q;
                bv[nt][0] = fbits(wb[c * LDP + kc + tq]);
                bv[nt][1] = fbits(wb[c * LDP + kc + 4 + tq]);
            }
#pragma unroll
            for (int mt = 0; mt < 2; mt++)
#pragma unroll
                for (int nt = 0; nt < 4; nt++)
                    mma8(acc[mt][nt], a[mt], bv[nt]);
        }
        if (kt + 1 < NK) {
            store_smem(b ^ 1);
            __syncthreads();
        }
    }

    // epilogue: scale by combine weight, store g_y
#pragma unroll
    for (int mt = 0; mt < 2; mt++) {
#pragma unroll
        for (int half = 0; half < 2; half++) {
            int m = m0 + wM * 32 + mt * 16 + q + half * 8;
            if (m >= count) continue;
            float cw = g_slot_w[off + m];
            float* yrow = g_y + (size_t)(off + m) * H + n0 + wN * 32;
#pragma unroll
            for (int nt = 0; nt < 4; nt++) {
                float2 o;
                o.x = cw * acc[mt][nt][half * 2 + 0];
                o.y = cw * acc[mt][nt][half * 2 + 1];
                *(float2*)(yrow + nt * 8 + 2 * tq) = o;
            }
        }
    }
}

// ---------------------------------------------------------------------------
// 7. combine: out[t] = sum of the token's K slot rows (fixed order)
// ---------------------------------------------------------------------------
__global__ void combine_kernel(float* __restrict__ out) {
    int t = blockIdx.x;
    const float4* r0 = (const float4*)(g_y + (size_t)g_token_slot[t * K + 0] * H);
    const float4* r1 = (const float4*)(g_y + (size_t)g_token_slot[t * K + 1] * H);
    const float4* r2 = (const float4*)(g_y + (size_t)g_token_slot[t * K + 2] * H);
    const float4* r3 = (const float4*)(g_y + (size_t)g_token_slot[t * K + 3] * H);
    float4* o = (float4*)(out + (size_t)t * H);
    for (int h = threadIdx.x; h < H / 4; h += blockDim.x) {
        float4 a = r0[h], b = r1[h], c = r2[h], d = r3[h];
        float4 v;
        v.x = a.x + b.x + c.x + d.x;
        v.y = a.y + b.y + c.y + d.y;
        v.z = a.z + b.z + c.z + d.z;
        v.w = a.w + b.w + c.w + d.w;
        o[h] = v;
    }
}

// ---------------------------------------------------------------------------
extern "C" void kernel_launch(void* const* d_in, const int* in_sizes, int n_in,
                              void* d_out, int out_size) {
    const float* x    = (const float*)d_in[0];
    const float* gw   = (const float*)d_in[1];
    const float* bias = (const float*)d_in[2];
    const float* w1   = (const float*)d_in[3];
    const float* w3   = (const float*)d_in[4];
    const float* w2   = (const float*)d_in[5];
    float* out = (float*)d_out;

    const int G1_SMEM = (2 * BM * LDP + 4 * BN * LDP) * 4;   // 51200 B
    cudaFuncSetAttribute(gemm1_tc, cudaFuncAttributeMaxDynamicSharedMemorySize, G1_SMEM);

    init_kernel<<<1, 32>>>();
    router_kernel<<<(T * 32 + 255) / 256, 256>>>(x, gw, bias);
    scan_kernel<<<1, 1>>>();
    scatter_kernel<<<(S + 255) / 256, 256>>>();

    // grid: x = M-tiles (fastest -> consecutive CTAs share weight slice in L2)
    gemm1_tc<<<dim3(T / BM, F / BN, E), 256, G1_SMEM>>>(x, w1, w3);
    gemm2_tc<<<dim3(T / BM, H / BN, E), 256>>>(w2);

    combine_kernel<<<T, 256>>>(out);
}

// round 6
// speedup vs baseline: 3.4470x; 1.1278x over previous
#include <cuda_runtime.h>
#include <cstdint>
#include <math.h>

#define T 4096
#define H 1024
#define F 512
#define E 16
#define K 4
#define S (T*K)

// ---------------- scratch (device globals; no runtime allocation) ----------
__device__ int    g_topi[S];
__device__ float  g_topw[S];
__device__ int    g_counts[E];
__device__ int    g_off[E + 1];
__device__ int    g_cursor[E];
__device__ int    g_slot_token[S];
__device__ float  g_slot_w[S];
__device__ int    g_token_slot[S];
__device__ float  g_h[(size_t)S * F];     // SwiGLU acts (tf32-rounded, k-permuted)
__device__ float  g_y[(size_t)S * H];     // per-slot weighted expert output
// pre-rounded (tf32, RNA) + k-permuted operands
__device__ float  g_xt [(size_t)T * H];
__device__ float  g_w1t[(size_t)E * F * H];
__device__ float  g_w3t[(size_t)E * F * H];
__device__ float  g_w2t[(size_t)E * H * F];

// ---------------- helpers ---------------------------------------------------
__device__ __forceinline__ float rna_tf32(float v) {
    uint32_t r;
    asm("cvt.rna.tf32.f32 %0, %1;" : "=r"(r) : "f"(v));
    return __uint_as_float(r);
}
__device__ __forceinline__ void mma8(float* d, const uint32_t* a, const uint32_t* b) {
    asm volatile(
        "mma.sync.aligned.m16n8k8.row.col.f32.tf32.tf32.f32 "
        "{%0,%1,%2,%3}, {%4,%5,%6,%7}, {%8,%9}, {%0,%1,%2,%3};"
        : "+f"(d[0]), "+f"(d[1]), "+f"(d[2]), "+f"(d[3])
        : "r"(a[0]), "r"(a[1]), "r"(a[2]), "r"(a[3]), "r"(b[0]), "r"(b[1]));
}
__device__ __forceinline__ uint32_t fbits(float v) { return __float_as_uint(v); }
__device__ __forceinline__ uint32_t smem_u32(const void* p) {
    uint32_t a;
    asm("{ .reg .u64 t; cvta.to.shared.u64 t, %1; cvt.u32.u64 %0, t; }"
        : "=r"(a) : "l"(p));
    return a;
}
__device__ __forceinline__ void cp_async16(uint32_t dst, const void* src) {
    asm volatile("cp.async.cg.shared.global [%0], [%1], 16;" :: "r"(dst), "l"(src));
}
#define CP_COMMIT() asm volatile("cp.async.commit_group;" ::: "memory")
#define CP_WAIT2()  asm volatile("cp.async.wait_group 2;" ::: "memory")

#define BK  16
#define LDK 24      // padded row stride (floats); conflict-free LDS.64 frags
#define STG1 ((64 + 128 + 128) * LDK)   // 7680 floats / stage (gemm1)
#define STG2 ((64 + 128) * LDK)         // 4608 floats / stage (gemm2)

// ---------------------------------------------------------------------------
// 0. prepass: RNA-round to tf32 and permute k within every 8-group:
//    dst8 = {s0,s4,s1,s5,s2,s6,s3,s7}  (pos(k) = (k&3)*2 + (k>>2))
// ---------------------------------------------------------------------------
__device__ __forceinline__ void perm8(const float4* __restrict__ src,
                                      float4* __restrict__ dst, size_t i) {
    float4 a = src[2 * i], b = src[2 * i + 1];
    float4 o0, o1;
    o0.x = rna_tf32(a.x); o0.y = rna_tf32(b.x);
    o0.z = rna_tf32(a.y); o0.w = rna_tf32(b.y);
    o1.x = rna_tf32(a.z); o1.y = rna_tf32(b.z);
    o1.z = rna_tf32(a.w); o1.w = rna_tf32(b.w);
    dst[2 * i] = o0; dst[2 * i + 1] = o1;
}
__global__ void prep_kernel(const float4* __restrict__ x,
                            const float4* __restrict__ w1,
                            const float4* __restrict__ w3,
                            const float4* __restrict__ w2) {
    size_t i0 = blockIdx.x * blockDim.x + threadIdx.x;
    size_t stride = (size_t)gridDim.x * blockDim.x;
    const size_t nx = (size_t)T * H / 8, nw = (size_t)E * F * H / 8;
    for (size_t i = i0; i < nx; i += stride) perm8(x,  (float4*)g_xt,  i);
    for (size_t i = i0; i < nw; i += stride) perm8(w1, (float4*)g_w1t, i);
    for (size_t i = i0; i < nw; i += stride) perm8(w3, (float4*)g_w3t, i);
    for (size_t i = i0; i < nw; i += stride) perm8(w2, (float4*)g_w2t, i);
}

// ---------------------------------------------------------------------------
// 1. init / 2. router (exact fp32) / 3. scan / 4. scatter
// ---------------------------------------------------------------------------
__global__ void init_kernel() {
    int i = threadIdx.x;
    if (i < E) g_counts[i] = 0;
}

__global__ void router_kernel(const float* __restrict__ x,
                              const float* __restrict__ gw,
                              const float* __restrict__ bias) {
    int warp = (blockIdx.x * blockDim.x + threadIdx.x) >> 5;
    int lane = threadIdx.x & 31;
    if (warp >= T) return;

    const float* xr = x + (size_t)warp * H;
    float acc[E];
#pragma unroll
    for (int e = 0; e < E; e++) acc[e] = 0.f;
    for (int h = lane; h < H; h += 32) {
        float xv = xr[h];
#pragma unroll
        for (int e = 0; e < E; e++)
            acc[e] = fmaf(xv, __ldg(&gw[e * H + h]), acc[e]);
    }
#pragma unroll
    for (int o = 16; o > 0; o >>= 1)
#pragma unroll
        for (int e = 0; e < E; e++)
            acc[e] += __shfl_xor_sync(0xffffffffu, acc[e], o);

    if (lane == 0) {
        float sc[E], sel[E];
#pragma unroll
        for (int e = 0; e < E; e++) {
            sc[e]  = 1.f / (1.f + expf(-acc[e]));
            sel[e] = sc[e] + bias[e];
        }
        bool used[E];
#pragma unroll
        for (int e = 0; e < E; e++) used[e] = false;
        float sum = 0.f;
        int   idx[K]; float w[K];
#pragma unroll
        for (int k = 0; k < K; k++) {
            float best = -1e30f; int bi = 0;
            for (int e = 0; e < E; e++)
                if (!used[e] && sel[e] > best) { best = sel[e]; bi = e; }
            used[bi] = true; idx[k] = bi; w[k] = sc[bi]; sum += sc[bi];
        }
        float inv = 1.f / sum;
#pragma unroll
        for (int k = 0; k < K; k++) {
            g_topi[warp * K + k] = idx[k];
            g_topw[warp * K + k] = w[k] * inv;
            atomicAdd(&g_counts[idx[k]], 1);
        }
    }
}

__global__ void scan_kernel() {
    int o = 0; g_off[0] = 0;
    for (int e = 0; e < E; e++) {
        o += g_counts[e];
        g_off[e + 1] = o;
        g_cursor[e]  = g_off[e];
    }
}

__global__ void scatter_kernel() {
    int i = blockIdx.x * blockDim.x + threadIdx.x;
    if (i >= S) return;
    int e   = g_topi[i];
    int pos = atomicAdd(&g_cursor[e], 1);
    g_slot_token[pos] = i >> 2;
    g_slot_w[pos]     = g_topw[i];
    g_token_slot[i]   = pos;
}

// ---------------------------------------------------------------------------
// 5. gemm1: P1 = X@W1^T, P3 = X@W3^T, h = silu(P1)*P3
//    CTA 64x128, warps 2Mx4N (32x32), BK=16, cp.async 3-stage, LDS.64 frags
// ---------------------------------------------------------------------------
__global__ __launch_bounds__(256, 2) void gemm1_tc() {
    int e     = blockIdx.z;
    int off   = g_off[e];
    int count = g_off[e + 1] - off;
    int m0    = blockIdx.x * 64;
    if (m0 >= count) return;
    int n0 = blockIdx.y * 128;

    extern __shared__ float sm[];
    __shared__ int toks[64];

    int tid = threadIdx.x, wid = tid >> 5, lane = tid & 31;
    int q = lane >> 2, tq = lane & 3;
    int wM = wid & 1, wN = wid >> 1;

    if (tid < 64) toks[tid] = g_slot_token[off + min(m0 + tid, count - 1)];
    __syncthreads();

    const float* w1e = g_w1t + ((size_t)e * F + n0) * H;
    const float* w3e = g_w3t + ((size_t)e * F + n0) * H;

    uint32_t sbase = smem_u32(sm);
    int crow = tid >> 2, cc4 = (tid & 3) * 4;    // chunk row / col(floats)
    int crow2 = 64 + crow;

    auto load_stage = [&](int kt, int buf) {
        uint32_t sb = sbase + (uint32_t)buf * STG1 * 4;
        int kf = kt * BK + cc4;
        cp_async16(sb + (crow * LDK + cc4) * 4,
                   g_xt + (size_t)toks[crow] * H + kf);
        cp_async16(sb + (1536 + crow  * LDK + cc4) * 4, w1e + (size_t)crow  * H + kf);
        cp_async16(sb + (1536 + crow2 * LDK + cc4) * 4, w1e + (size_t)crow2 * H + kf);
        cp_async16(sb + (4608 + crow  * LDK + cc4) * 4, w3e + (size_t)crow  * H + kf);
        cp_async16(sb + (4608 + crow2 * LDK + cc4) * 4, w3e + (size_t)crow2 * H + kf);
    };

    float acc1[2][4][4] = {}, acc3[2][4][4] = {};

    load_stage(0, 0); CP_COMMIT();
    load_stage(1, 1); CP_COMMIT();

    const int NK = H / BK;   // 64
    for (int kt = 0; kt < NK; kt++) {
        int buf = kt % 3;
        __syncthreads();                         // prev compute done everywhere
        if (kt + 2 < NK) load_stage(kt + 2, (kt + 2) % 3);
        CP_COMMIT();
        CP_WAIT2();                              // stage kt complete
        __syncthreads();

        const float* xb = sm + buf * STG1;
        const float* b1 = xb + 1536;
        const float* b3 = xb + 4608;
#pragma unroll
        for (int ks = 0; ks < 2; ks++) {
            int kb = ks * 8 + 2 * tq;
            uint32_t a[2][4];
#pragma unroll
            for (int mt = 0; mt < 2; mt++) {
                int r = wM * 32 + mt * 16 + q;
                float2 v0 = *(const float2*)(xb + r * LDK + kb);
                float2 v1 = *(const float2*)(xb + (r + 8) * LDK + kb);
                a[mt][0] = fbits(v0.x); a[mt][1] = fbits(v1.x);
                a[mt][2] = fbits(v0.y); a[mt][3] = fbits(v1.y);
            }
#pragma unroll
            for (int nt = 0; nt < 4; nt++) {
                int c = wN * 32 + nt * 8 + q;
                float2 u1 = *(const float2*)(b1 + c * LDK + kb);
                float2 u3 = *(const float2*)(b3 + c * LDK + kb);
                uint32_t bb1[2] = { fbits(u1.x), fbits(u1.y) };
                uint32_t bb3[2] = { fbits(u3.x), fbits(u3.y) };
#pragma unroll
                for (int mt = 0; mt < 2; mt++) {
                    mma8(acc1[mt][nt], a[mt], bb1);
                    mma8(acc3[mt][nt], a[mt], bb3);
                }
            }
        }
    }

    // epilogue: SwiGLU, RNA-round, store k-PERMUTED h (gemm2 operand layout)
#pragma unroll
    for (int mt = 0; mt < 2; mt++) {
#pragma unroll
        for (int half = 0; half < 2; half++) {
            int m = m0 + wM * 32 + mt * 16 + q + half * 8;
            if (m >= count) continue;
            float* hrow = g_h + (size_t)(off + m) * F + n0 + wN * 32;
#pragma unroll
            for (int nt = 0; nt < 4; nt++) {
#pragma unroll
                for (int ee = 0; ee < 2; ee++) {
                    int l = 2 * tq + ee;
                    int p = (l & 3) * 2 + (l >> 2);
                    float g = acc1[mt][nt][half * 2 + ee];
                    float u = acc3[mt][nt][half * 2 + ee];
                    hrow[nt * 8 + p] = rna_tf32((g / (1.f + expf(-g))) * u);
                }
            }
        }
    }
}

// ---------------------------------------------------------------------------
// 6. gemm2: y = c * (h @ W2^T).  CTA 64x128, same structure, NK = F/16 = 32
// ---------------------------------------------------------------------------
__global__ __launch_bounds__(256, 2) void gemm2_tc() {
    int e     = blockIdx.z;
    int off   = g_off[e];
    int count = g_off[e + 1] - off;
    int m0    = blockIdx.x * 64;
    if (m0 >= count) return;
    int n0 = blockIdx.y * 128;

    extern __shared__ float sm[];

    int tid = threadIdx.x, wid = tid >> 5, lane = tid & 31;
    int q = lane >> 2, tq = lane & 3;
    int wM = wid & 1, wN = wid >> 1;

    const float* w2e = g_w2t + ((size_t)e * H + n0) * F;
    int cm1 = count - 1;

    uint32_t sbase = smem_u32(sm);
    int crow = tid >> 2, cc4 = (tid & 3) * 4;
    int crow2 = 64 + crow;
    int arow = off + min(m0 + crow, cm1);

    auto load_stage = [&](int kt, int buf) {
        uint32_t sb = sbase + (uint32_t)buf * STG2 * 4;
        int kf = kt * BK + cc4;
        cp_async16(sb + (crow * LDK + cc4) * 4, g_h + (size_t)arow * F + kf);
        cp_async16(sb + (1536 + crow  * LDK + cc4) * 4, w2e + (size_t)crow  * F + kf);
        cp_async16(sb + (1536 + crow2 * LDK + cc4) * 4, w2e + (size_t)crow2 * F + kf);
    };

    float acc[2][4][4] = {};

    load_stage(0, 0); CP_COMMIT();
    load_stage(1, 1); CP_COMMIT();

    const int NK = F / BK;   // 32
    for (int kt = 0; kt < NK; kt++) {
        int buf = kt % 3;
        __syncthreads();
        if (kt + 2 < NK) load_stage(kt + 2, (kt + 2) % 3);
        CP_COMMIT();
        CP_WAIT2();
        __syncthreads();

        const float* hb = sm + buf * STG2;
        const float* wb = hb + 1536;
#pragma unroll
        for (int ks = 0; ks < 2; ks++) {
            int kb = ks * 8 + 2 * tq;
            uint32_t a[2][4];
#pragma unroll
            for (int mt = 0; mt < 2; mt++) {
                int r = wM * 32 + mt * 16 + q;
                float2 v0 = *(const float2*)(hb + r * LDK + kb);
                float2 v1 = *(const float2*)(hb + (r + 8) * LDK + kb);
                a[mt][0] = fbits(v0.x); a[mt][1] = fbits(v1.x);
                a[mt][2] = fbits(v0.y); a[mt][3] = fbits(v1.y);
            }
#pragma unroll
            for (int nt = 0; nt < 4; nt++) {
                int c = wN * 32 + nt * 8 + q;
                float2 u = *(const float2*)(wb + c * LDK + kb);
                uint32_t bb[2] = { fbits(u.x), fbits(u.y) };
#pragma unroll
                for (int mt = 0; mt < 2; mt++)
                    mma8(acc[mt][nt], a[mt], bb);
            }
        }
    }

    // epilogue: scale by combine weight, store g_y (normal layout)
#pragma unroll
    for (int mt = 0; mt < 2; mt++) {
#pragma unroll
        for (int half = 0; half < 2; half++) {
            int m = m0 + wM * 32 + mt * 16 + q + half * 8;
            if (m >= count) continue;
            float cw = g_slot_w[off + m];
            float* yrow = g_y + (size_t)(off + m) * H + n0 + wN * 32;
#pragma unroll
            for (int nt = 0; nt < 4; nt++) {
                float2 o;
                o.x = cw * acc[mt][nt][half * 2 + 0];
                o.y = cw * acc[mt][nt][half * 2 + 1];
                *(float2*)(yrow + nt * 8 + 2 * tq) = o;
            }
        }
    }
}

// ---------------------------------------------------------------------------
// 7. combine: out[t] = sum of the token's K slot rows (fixed order)
// ---------------------------------------------------------------------------
__global__ void combine_kernel(float* __restrict__ out) {
    int t = blockIdx.x;
    const float4* r0 = (const float4*)(g_y + (size_t)g_token_slot[t * K + 0] * H);
    const float4* r1 = (const float4*)(g_y + (size_t)g_token_slot[t * K + 1] * H);
    const float4* r2 = (const float4*)(g_y + (size_t)g_token_slot[t * K + 2] * H);
    const float4* r3 = (const float4*)(g_y + (size_t)g_token_slot[t * K + 3] * H);
    float4* o = (float4*)(out + (size_t)t * H);
    for (int h = threadIdx.x; h < H / 4; h += blockDim.x) {
        float4 a = r0[h], b = r1[h], c = r2[h], d = r3[h];
        float4 v;
        v.x = a.x + b.x + c.x + d.x;
        v.y = a.y + b.y + c.y + d.y;
        v.z = a.z + b.z + c.z + d.z;
        v.w = a.w + b.w + c.w + d.w;
        o[h] = v;
    }
}

// ---------------------------------------------------------------------------
extern "C" void kernel_launch(void* const* d_in, const int* in_sizes, int n_in,
                              void* d_out, int out_size) {
    const float* x    = (const float*)d_in[0];
    const float* gw   = (const float*)d_in[1];
    const float* bias = (const float*)d_in[2];
    const float* w1   = (const float*)d_in[3];
    const float* w3   = (const float*)d_in[4];
    const float* w2   = (const float*)d_in[5];
    float* out = (float*)d_out;

    const int SM1 = STG1 * 3 * 4;   // 92160 B
    const int SM2 = STG2 * 3 * 4;   // 55296 B
    cudaFuncSetAttribute(gemm1_tc, cudaFuncAttributeMaxDynamicSharedMemorySize, SM1);
    cudaFuncSetAttribute(gemm2_tc, cudaFuncAttributeMaxDynamicSharedMemorySize, SM2);

    prep_kernel<<<1024, 256>>>((const float4*)x, (const float4*)w1,
                               (const float4*)w3, (const float4*)w2);
    init_kernel<<<1, 32>>>();
    router_kernel<<<(T * 32 + 255) / 256, 256>>>(x, gw, bias);
    scan_kernel<<<1, 1>>>();
    scatter_kernel<<<(S + 255) / 256, 256>>>();

    gemm1_tc<<<dim3(T / 64, F / 128, E), 256, SM1>>>();
    gemm2_tc<<<dim3(T / 64, H / 128, E), 256, SM2>>>();

    combine_kernel<<<T, 256>>>(out);
}

// round 7
// speedup vs baseline: 5.1774x; 1.5020x over previous
#include <cuda_runtime.h>
#include <cuda_fp16.h>
#include <cstdint>
#include <math.h>

#define T 4096
#define H 1024
#define F 512
#define E 16
#define K 4
#define S (T*K)

// ---------------- scratch (device globals; no runtime allocation) ----------
__device__ int    g_topi[S];
__device__ float  g_topw[S];
__device__ int    g_counts[E];
__device__ int    g_off[E + 1];
__device__ int    g_cursor[E];
__device__ int    g_slot_token[S];
__device__ float  g_slot_w[S];
__device__ int    g_token_slot[S];
__device__ float  g_y[(size_t)S * H];               // per-slot weighted output
// fp16 (RN) + pair-permuted operands / activations
__device__ __align__(256) __half g_xh [(size_t)T * H];
__device__ __align__(256) __half g_w1h[(size_t)E * F * H];
__device__ __align__(256) __half g_w3h[(size_t)E * F * H];
__device__ __align__(256) __half g_w2h[(size_t)E * H * F];
__device__ __align__(256) __half g_hh [(size_t)S * F];

// ---------------- helpers ---------------------------------------------------
__device__ __forceinline__ void mma16(float* d, const uint32_t* a,
                                      uint32_t b0, uint32_t b1) {
    asm volatile(
        "mma.sync.aligned.m16n8k16.row.col.f32.f16.f16.f32 "
        "{%0,%1,%2,%3}, {%4,%5,%6,%7}, {%8,%9}, {%0,%1,%2,%3};"
        : "+f"(d[0]), "+f"(d[1]), "+f"(d[2]), "+f"(d[3])
        : "r"(a[0]), "r"(a[1]), "r"(a[2]), "r"(a[3]), "r"(b0), "r"(b1));
}
__device__ __forceinline__ uint32_t smem_u32(const void* p) {
    uint32_t a;
    asm("{ .reg .u64 t; cvta.to.shared.u64 t, %1; cvt.u32.u64 %0, t; }"
        : "=r"(a) : "l"(p));
    return a;
}
__device__ __forceinline__ void cp_async16(uint32_t dst, const void* src) {
    asm volatile("cp.async.cg.shared.global [%0], [%1], 16;" :: "r"(dst), "l"(src));
}
#define CP_COMMIT() asm volatile("cp.async.commit_group;" ::: "memory")
#define CP_WAIT3()  asm volatile("cp.async.wait_group 3;" ::: "memory")

// stage sizes in BYTES (unpadded 32B rows, BK = 16 halves)
#define STG1B 10240     // x 2KB + w1 4KB + w3 4KB
#define STG2B 6144      // h 2KB + w2 4KB

// ---------------------------------------------------------------------------
// 0. prepass: fp32 -> fp16 (RN) + pair permutation within every 16-k group:
//    pair order {p0,p4,p1,p5,p2,p6,p3,p7}  (pos(p) = (p&3)*2 + (p>>2))
//    Makes each mma fragment (pairs tq and tq+4) one contiguous 8B LDS.64.
//    Also zeroes g_counts (replaces init_kernel).
// ---------------------------------------------------------------------------
__device__ __forceinline__ void conv16(const float4* __restrict__ src,
                                       uint4* __restrict__ dst, size_t g) {
    float4 f0 = src[4 * g + 0], f1 = src[4 * g + 1];
    float4 f2 = src[4 * g + 2], f3 = src[4 * g + 3];
    __half2 h0 = __floats2half2_rn(f0.x, f0.y), h1 = __floats2half2_rn(f0.z, f0.w);
    __half2 h2 = __floats2half2_rn(f1.x, f1.y), h3 = __floats2half2_rn(f1.z, f1.w);
    __half2 h4 = __floats2half2_rn(f2.x, f2.y), h5 = __floats2half2_rn(f2.z, f2.w);
    __half2 h6 = __floats2half2_rn(f3.x, f3.y), h7 = __floats2half2_rn(f3.z, f3.w);
    __half2 o[8] = { h0, h4, h1, h5, h2, h6, h3, h7 };
    dst[2 * g + 0] = *(uint4*)&o[0];
    dst[2 * g + 1] = *(uint4*)&o[4];
}
__global__ void prep_kernel(const float4* __restrict__ x,
                            const float4* __restrict__ w1,
                            const float4* __restrict__ w3,
                            const float4* __restrict__ w2) {
    if (blockIdx.x == 0 && threadIdx.x < E) g_counts[threadIdx.x] = 0;
    size_t i0 = blockIdx.x * blockDim.x + threadIdx.x;
    size_t stride = (size_t)gridDim.x * blockDim.x;
    const size_t nx = (size_t)T * H / 16, nw = (size_t)E * F * H / 16;
    for (size_t i = i0; i < nx; i += stride) conv16(x,  (uint4*)g_xh,  i);
    for (size_t i = i0; i < nw; i += stride) conv16(w1, (uint4*)g_w1h, i);
    for (size_t i = i0; i < nw; i += stride) conv16(w3, (uint4*)g_w3h, i);
    for (size_t i = i0; i < nw; i += stride) conv16(w2, (uint4*)g_w2h, i);
}

// ---------------------------------------------------------------------------
// 1. router (exact fp32) / 2. scan / 3. scatter
// ---------------------------------------------------------------------------
__global__ void router_kernel(const float* __restrict__ x,
                              const float* __restrict__ gw,
                              const float* __restrict__ bias) {
    int warp = (blockIdx.x * blockDim.x + threadIdx.x) >> 5;
    int lane = threadIdx.x & 31;
    if (warp >= T) return;

    const float* xr = x + (size_t)warp * H;
    float acc[E];
#pragma unroll
    for (int e = 0; e < E; e++) acc[e] = 0.f;
    for (int h = lane; h < H; h += 32) {
        float xv = xr[h];
#pragma unroll
        for (int e = 0; e < E; e++)
            acc[e] = fmaf(xv, __ldg(&gw[e * H + h]), acc[e]);
    }
#pragma unroll
    for (int o = 16; o > 0; o >>= 1)
#pragma unroll
        for (int e = 0; e < E; e++)
            acc[e] += __shfl_xor_sync(0xffffffffu, acc[e], o);

    if (lane == 0) {
        float sc[E], sel[E];
#pragma unroll
        for (int e = 0; e < E; e++) {
            sc[e]  = 1.f / (1.f + expf(-acc[e]));
            sel[e] = sc[e] + bias[e];
        }
        bool used[E];
#pragma unroll
        for (int e = 0; e < E; e++) used[e] = false;
        float sum = 0.f;
        int   idx[K]; float w[K];
#pragma unroll
        for (int k = 0; k < K; k++) {
            float best = -1e30f; int bi = 0;
            for (int e = 0; e < E; e++)
                if (!used[e] && sel[e] > best) { best = sel[e]; bi = e; }
            used[bi] = true; idx[k] = bi; w[k] = sc[bi]; sum += sc[bi];
        }
        float inv = 1.f / sum;
#pragma unroll
        for (int k = 0; k < K; k++) {
            g_topi[warp * K + k] = idx[k];
            g_topw[warp * K + k] = w[k] * inv;
            atomicAdd(&g_counts[idx[k]], 1);
        }
    }
}

__global__ void scan_kernel() {
    int o = 0; g_off[0] = 0;
    for (int e = 0; e < E; e++) {
        o += g_counts[e];
        g_off[e + 1] = o;
        g_cursor[e]  = g_off[e];
    }
}

__global__ void scatter_kernel() {
    int i = blockIdx.x * blockDim.x + threadIdx.x;
    if (i >= S) return;
    int e   = g_topi[i];
    int pos = atomicAdd(&g_cursor[e], 1);
    g_slot_token[pos] = i >> 2;
    g_slot_w[pos]     = g_topw[i];
    g_token_slot[i]   = pos;
}

// ---------------------------------------------------------------------------
// 4. gemm1 (fp16 m16n8k16): P1 = X@W1^T, P3 = X@W3^T, h = silu(P1)*P3
//    CTA 64x128, warps 2Mx4N (32x32), BK=16, 4-stage cp.async
// ---------------------------------------------------------------------------
__global__ __launch_bounds__(256, 2) void gemm1_tc() {
    int e     = blockIdx.z;
    int off   = g_off[e];
    int count = g_off[e + 1] - off;
    int m0    = blockIdx.x * 64;
    if (m0 >= count) return;
    int n0 = blockIdx.y * 128;

    extern __shared__ __half smh[];
    __shared__ int toks[64];

    int tid = threadIdx.x, wid = tid >> 5, lane = tid & 31;
    int q = lane >> 2, tq = lane & 3;
    int wM = wid & 1, wN = wid >> 1;

    if (tid < 64) toks[tid] = g_slot_token[off + min(m0 + tid, count - 1)];
    __syncthreads();

    const __half* w1e = g_w1h + ((size_t)e * F + n0) * H;
    const __half* w3e = g_w3h + ((size_t)e * F + n0) * H;

    uint32_t sb0 = smem_u32(smh);
    int lrow = tid >> 1, lseg = tid & 1;          // 16B segments, 32B rows

    auto load_stage = [&](int kt, int buf) {
        uint32_t sb = sb0 + (uint32_t)buf * STG1B;
        int kf = kt * 16 + lseg * 8;
        if (tid < 128)
            cp_async16(sb + lrow * 32 + lseg * 16,
                       g_xh + (size_t)toks[lrow] * H + kf);
        cp_async16(sb + 2048 + lrow * 32 + lseg * 16, w1e + (size_t)lrow * H + kf);
        cp_async16(sb + 6144 + lrow * 32 + lseg * 16, w3e + (size_t)lrow * H + kf);
    };

    float acc1[2][4][4] = {}, acc3[2][4][4] = {};

    load_stage(0, 0); CP_COMMIT();
    load_stage(1, 1); CP_COMMIT();
    load_stage(2, 2); CP_COMMIT();

    const int NK = H / 16;   // 64
    for (int kt = 0; kt < NK; kt++) {
        __syncthreads();                          // prev compute done everywhere
        if (kt + 3 < NK) load_stage(kt + 3, (kt + 3) & 3);
        CP_COMMIT();
        CP_WAIT3();                               // stage kt complete
        __syncthreads();

        const __half* xb = smh + (size_t)(kt & 3) * (STG1B / 2);
        const __half* b1 = xb + 1024;
        const __half* b3 = xb + 3072;

        uint32_t a[2][4];
#pragma unroll
        for (int mt = 0; mt < 2; mt++) {
            int r = wM * 32 + mt * 16 + q;
            uint2 v0 = *(const uint2*)(xb + r * 16 + 4 * tq);
            uint2 v1 = *(const uint2*)(xb + (r + 8) * 16 + 4 * tq);
            a[mt][0] = v0.x; a[mt][2] = v0.y;
            a[mt][1] = v1.x; a[mt][3] = v1.y;
        }
#pragma unroll
        for (int nt = 0; nt < 4; nt++) {
            int c = wN * 32 + nt * 8 + q;
            uint2 u1 = *(const uint2*)(b1 + c * 16 + 4 * tq);
            uint2 u3 = *(const uint2*)(b3 + c * 16 + 4 * tq);
#pragma unroll
            for (int mt = 0; mt < 2; mt++) {
                mma16(acc1[mt][nt], a[mt], u1.x, u1.y);
                mma16(acc3[mt][nt], a[mt], u3.x, u3.y);
            }
        }
    }

    // epilogue: SwiGLU -> g_hh as fp16, PAIR-PERMUTED (gemm2 operand layout)
#pragma unroll
    for (int mt = 0; mt < 2; mt++) {
#pragma unroll
        for (int hf = 0; hf < 2; hf++) {
            int m = m0 + wM * 32 + mt * 16 + q + hf * 8;
            if (m >= count) continue;
            __half* hrow = g_hh + (size_t)(off + m) * F + n0;
#pragma unroll
            for (int nt = 0; nt < 4; nt++) {
                float g0 = acc1[mt][nt][hf * 2 + 0];
                float g1 = acc1[mt][nt][hf * 2 + 1];
                float u0 = acc3[mt][nt][hf * 2 + 0];
                float u1 = acc3[mt][nt][hf * 2 + 1];
                float h0 = (g0 / (1.f + expf(-g0))) * u0;
                float h1 = (g1 / (1.f + expf(-g1))) * u1;
                // pair p = tq + (nt&1)*4 within 16-col group -> offset 4tq+2(nt&1)
                int cb = wN * 32 + (nt >> 1) * 16 + 4 * tq + 2 * (nt & 1);
                *(__half2*)(hrow + cb) = __floats2half2_rn(h0, h1);
            }
        }
    }
}

// ---------------------------------------------------------------------------
// 5. gemm2 (fp16 m16n8k16): y = c * (h @ W2^T).  CTA 64x128, NK = F/16 = 32
// ---------------------------------------------------------------------------
__global__ __launch_bounds__(256, 2) void gemm2_tc() {
    int e     = blockIdx.z;
    int off   = g_off[e];
    int count = g_off[e + 1] - off;
    int m0    = blockIdx.x * 64;
    if (m0 >= count) return;
    int n0 = blockIdx.y * 128;

    extern __shared__ __half smh[];

    int tid = threadIdx.x, wid = tid >> 5, lane = tid & 31;
    int q = lane >> 2, tq = lane & 3;
    int wM = wid & 1, wN = wid >> 1;

    const __half* w2e = g_w2h + ((size_t)e * H + n0) * F;
    int cm1 = count - 1;

    uint32_t sb0 = smem_u32(smh);
    int lrow = tid >> 1, lseg = tid & 1;
    int arow = off + min(m0 + lrow, cm1);         // only used when tid<128

    auto load_stage = [&](int kt, int buf) {
        uint32_t sb = sb0 + (uint32_t)buf * STG2B;
        int kf = kt * 16 + lseg * 8;
        if (tid < 128)
            cp_async16(sb + lrow * 32 + lseg * 16,
                       g_hh + (size_t)arow * F + kf);
        cp_async16(sb + 2048 + lrow * 32 + lseg * 16, w2e + (size_t)lrow * F + kf);
    };

    float acc[2][4][4] = {};

    load_stage(0, 0); CP_COMMIT();
    load_stage(1, 1); CP_COMMIT();
    load_stage(2, 2); CP_COMMIT();

    const int NK = F / 16;   // 32
    for (int kt = 0; kt < NK; kt++) {
        __syncthreads();
        if (kt + 3 < NK) load_stage(kt + 3, (kt + 3) & 3);
        CP_COMMIT();
        CP_WAIT3();
        __syncthreads();

        const __half* hb = smh + (size_t)(kt & 3) * (STG2B / 2);
        const __half* wb = hb + 1024;

        uint32_t a[2][4];
#pragma unroll
        for (int mt = 0; mt < 2; mt++) {
            int r = wM * 32 + mt * 16 + q;
            uint2 v0 = *(const uint2*)(hb + r * 16 + 4 * tq);
            uint2 v1 = *(const uint2*)(hb + (r + 8) * 16 + 4 * tq);
            a[mt][0] = v0.x; a[mt][2] = v0.y;
            a[mt][1] = v1.x; a[mt][3] = v1.y;
        }
#pragma unroll
        for (int nt = 0; nt < 4; nt++) {
            int c = wN * 32 + nt * 8 + q;
            uint2 u = *(const uint2*)(wb + c * 16 + 4 * tq);
#pragma unroll
            for (int mt = 0; mt < 2; mt++)
                mma16(acc[mt][nt], a[mt], u.x, u.y);
        }
    }

    // epilogue: scale by combine weight, store g_y fp32 (normal layout)
#pragma unroll
    for (int mt = 0; mt < 2; mt++) {
#pragma unroll
        for (int hf = 0; hf < 2; hf++) {
            int m = m0 + wM * 32 + mt * 16 + q + hf * 8;
            if (m >= count) continue;
            float cw = g_slot_w[off + m];
            float* yrow = g_y + (size_t)(off + m) * H + n0 + wN * 32;
#pragma unroll
            for (int nt = 0; nt < 4; nt++) {
                float2 o;
                o.x = cw * acc[mt][nt][hf * 2 + 0];
                o.y = cw * acc[mt][nt][hf * 2 + 1];
                *(float2*)(yrow + nt * 8 + 2 * tq) = o;
            }
        }
    }
}

// ---------------------------------------------------------------------------
// 6. combine: out[t] = sum of the token's K slot rows (fixed order)
// ---------------------------------------------------------------------------
__global__ void combine_kernel(float* __restrict__ out) {
    int t = blockIdx.x;
    const float4* r0 = (const float4*)(g_y + (size_t)g_token_slot[t * K + 0] * H);
    const float4* r1 = (const float4*)(g_y + (size_t)g_token_slot[t * K + 1] * H);
    const float4* r2 = (const float4*)(g_y + (size_t)g_token_slot[t * K + 2] * H);
    const float4* r3 = (const float4*)(g_y + (size_t)g_token_slot[t * K + 3] * H);
    float4* o = (float4*)(out + (size_t)t * H);
    for (int h = threadIdx.x; h < H / 4; h += blockDim.x) {
        float4 a = r0[h], b = r1[h], c = r2[h], d = r3[h];
        float4 v;
        v.x = a.x + b.x + c.x + d.x;
        v.y = a.y + b.y + c.y + d.y;
        v.z = a.z + b.z + c.z + d.z;
        v.w = a.w + b.w + c.w + d.w;
        o[h] = v;
    }
}

// ---------------------------------------------------------------------------
extern "C" void kernel_launch(void* const* d_in, const int* in_sizes, int n_in,
                              void* d_out, int out_size) {
    const float* x    = (const float*)d_in[0];
    const float* gw   = (const float*)d_in[1];
    const float* bias = (const float*)d_in[2];
    const float* w1   = (const float*)d_in[3];
    const float* w3   = (const float*)d_in[4];
    const float* w2   = (const float*)d_in[5];
    float* out = (float*)d_out;

    const int SM1 = 4 * STG1B;   // 40960 B
    const int SM2 = 4 * STG2B;   // 24576 B
    cudaFuncSetAttribute(gemm1_tc, cudaFuncAttributeMaxDynamicSharedMemorySize, SM1);
    cudaFuncSetAttribute(gemm2_tc, cudaFuncAttributeMaxDynamicSharedMemorySize, SM2);

    prep_kernel<<<1024, 256>>>((const float4*)x, (const float4*)w1,
                               (const float4*)w3, (const float4*)w2);
    router_kernel<<<(T * 32 + 255) / 256, 256>>>(x, gw, bias);
    scan_kernel<<<1, 1>>>();
    scatter_kernel<<<(S + 255) / 256, 256>>>();

    gemm1_tc<<<dim3(T / 64, F / 128, E), 256, SM1>>>();
    gemm2_tc<<<dim3(T / 64, H / 128, E), 256, SM2>>>();

    combine_kernel<<<T, 256>>>(out);
}

// round 8
// speedup vs baseline: 6.0355x; 1.1657x over previous
#include <cuda_runtime.h>
#include <cuda_fp16.h>
#include <cstdint>
#include <math.h>

#define T 4096
#define H 1024
#define F 512
#define E 16
#define K 4
#define S (T*K)

// ---------------- scratch (device globals; no runtime allocation) ----------
__device__ int    g_topi[S];
__device__ float  g_topw[S];
__device__ int    g_counts[E];
__device__ int    g_off[E + 1];
__device__ int    g_cursor[E];
__device__ int    g_slot_token[S];
__device__ float  g_slot_w[S];
__device__ int    g_token_slot[S];
// fp16 (RN) operands / activations / outputs (canonical layout, no permute)
__device__ __align__(256) __half g_xh [(size_t)T * H];
__device__ __align__(256) __half g_w1h[(size_t)E * F * H];
__device__ __align__(256) __half g_w3h[(size_t)E * F * H];
__device__ __align__(256) __half g_w2h[(size_t)E * H * F];
__device__ __align__(256) __half g_hh [(size_t)S * F];
__device__ __align__(256) __half g_yh [(size_t)S * H];

// ---------------- helpers ---------------------------------------------------
__device__ __forceinline__ void mma16(float* d, const uint32_t* a,
                                      uint32_t b0, uint32_t b1) {
    asm volatile(
        "mma.sync.aligned.m16n8k16.row.col.f32.f16.f16.f32 "
        "{%0,%1,%2,%3}, {%4,%5,%6,%7}, {%8,%9}, {%0,%1,%2,%3};"
        : "+f"(d[0]), "+f"(d[1]), "+f"(d[2]), "+f"(d[3])
        : "r"(a[0]), "r"(a[1]), "r"(a[2]), "r"(a[3]), "r"(b0), "r"(b1));
}
__device__ __forceinline__ void ldsm4(uint32_t* r, uint32_t addr) {
    asm volatile(
        "ldmatrix.sync.aligned.m8n8.x4.shared.b16 {%0,%1,%2,%3}, [%4];"
        : "=r"(r[0]), "=r"(r[1]), "=r"(r[2]), "=r"(r[3]) : "r"(addr));
}
__device__ __forceinline__ uint32_t smem_u32(const void* p) {
    uint32_t a;
    asm("{ .reg .u64 t; cvta.to.shared.u64 t, %1; cvt.u32.u64 %0, t; }"
        : "=r"(a) : "l"(p));
    return a;
}
__device__ __forceinline__ void cp_async16(uint32_t dst, const void* src) {
    asm volatile("cp.async.cg.shared.global [%0], [%1], 16;" :: "r"(dst), "l"(src));
}
#define CP_COMMIT() asm volatile("cp.async.commit_group;" ::: "memory")
#define CP_WAIT2()  asm volatile("cp.async.wait_group 2;" ::: "memory")

// XOR swizzle: rows are 32B; XOR bit7 into bit4 -> every 8-row x 16B LDSM
// phase and every cp.async write pattern is bank-conflict-free.
#define SWB(b) ((b) ^ ((((uint32_t)(b)) >> 3) & 0x10))

#define STG1B 10240     // x 2KB + w1 4KB + w3 4KB  (32B rows, BK=16 halves)
#define STG2B 6144      // h 2KB + w2 4KB

// ---------------------------------------------------------------------------
// 0. prepass: fp32 -> fp16 (RN), plain layout. Also zeroes g_counts.
// ---------------------------------------------------------------------------
__device__ __forceinline__ void conv8(const float4* __restrict__ src,
                                      uint4* __restrict__ dst, size_t i) {
    float4 f0 = src[2 * i], f1 = src[2 * i + 1];
    __half2 h0 = __floats2half2_rn(f0.x, f0.y), h1 = __floats2half2_rn(f0.z, f0.w);
    __half2 h2 = __floats2half2_rn(f1.x, f1.y), h3 = __floats2half2_rn(f1.z, f1.w);
    uint4 o;
    o.x = *(uint32_t*)&h0; o.y = *(uint32_t*)&h1;
    o.z = *(uint32_t*)&h2; o.w = *(uint32_t*)&h3;
    dst[i] = o;
}
__global__ void prep_kernel(const float4* __restrict__ x,
                            const float4* __restrict__ w1,
                            const float4* __restrict__ w3,
                            const float4* __restrict__ w2) {
    if (blockIdx.x == 0 && threadIdx.x < E) g_counts[threadIdx.x] = 0;
    size_t i0 = blockIdx.x * blockDim.x + threadIdx.x;
    size_t stride = (size_t)gridDim.x * blockDim.x;
    const size_t nx = (size_t)T * H / 8, nw = (size_t)E * F * H / 8;
    for (size_t i = i0; i < nx; i += stride) conv8(x,  (uint4*)g_xh,  i);
    for (size_t i = i0; i < nw; i += stride) conv8(w1, (uint4*)g_w1h, i);
    for (size_t i = i0; i < nw; i += stride) conv8(w3, (uint4*)g_w3h, i);
    for (size_t i = i0; i < nw; i += stride) conv8(w2, (uint4*)g_w2h, i);
}

// ---------------------------------------------------------------------------
// 1. router (exact fp32) / 2. scan / 3. scatter
// ---------------------------------------------------------------------------
__global__ void router_kernel(const float* __restrict__ x,
                              const float* __restrict__ gw,
                              const float* __restrict__ bias) {
    int warp = (blockIdx.x * blockDim.x + threadIdx.x) >> 5;
    int lane = threadIdx.x & 31;
    if (warp >= T) return;

    const float* xr = x + (size_t)warp * H;
    float acc[E];
#pragma unroll
    for (int e = 0; e < E; e++) acc[e] = 0.f;
    for (int h = lane; h < H; h += 32) {
        float xv = xr[h];
#pragma unroll
        for (int e = 0; e < E; e++)
            acc[e] = fmaf(xv, __ldg(&gw[e * H + h]), acc[e]);
    }
#pragma unroll
    for (int o = 16; o > 0; o >>= 1)
#pragma unroll
        for (int e = 0; e < E; e++)
            acc[e] += __shfl_xor_sync(0xffffffffu, acc[e], o);

    if (lane == 0) {
        float sc[E], sel[E];
#pragma unroll
        for (int e = 0; e < E; e++) {
            sc[e]  = 1.f / (1.f + expf(-acc[e]));
            sel[e] = sc[e] + bias[e];
        }
        bool used[E];
#pragma unroll
        for (int e = 0; e < E; e++) used[e] = false;
        float sum = 0.f;
        int   idx[K]; float w[K];
#pragma unroll
        for (int k = 0; k < K; k++) {
            float best = -1e30f; int bi = 0;
            for (int e = 0; e < E; e++)
                if (!used[e] && sel[e] > best) { best = sel[e]; bi = e; }
            used[bi] = true; idx[k] = bi; w[k] = sc[bi]; sum += sc[bi];
        }
        float inv = 1.f / sum;
#pragma unroll
        for (int k = 0; k < K; k++) {
            g_topi[warp * K + k] = idx[k];
            g_topw[warp * K + k] = w[k] * inv;
            atomicAdd(&g_counts[idx[k]], 1);
        }
    }
}

__global__ void scan_kernel() {
    int o = 0; g_off[0] = 0;
    for (int e = 0; e < E; e++) {
        o += g_counts[e];
        g_off[e + 1] = o;
        g_cursor[e]  = g_off[e];
    }
}

__global__ void scatter_kernel() {
    int i = blockIdx.x * blockDim.x + threadIdx.x;
    if (i >= S) return;
    int e   = g_topi[i];
    int pos = atomicAdd(&g_cursor[e], 1);
    g_slot_token[pos] = i >> 2;
    g_slot_w[pos]     = g_topw[i];
    g_token_slot[i]   = pos;
}

// ---------------------------------------------------------------------------
// ldmatrix address offsets (within a stage region, swizzled)
//   A frag (16x16 @ row r0): mats {r0..+7 k0-7, r0+8.. k0-7, r0.. k8-15, +8 k8-15}
//   B pair (16 n-rows @ c0): mats {c0.. k0-7, c0.. k8-15, c0+8.. k0-7, +8 k8-15}
// ---------------------------------------------------------------------------
__device__ __forceinline__ uint32_t a_off(int r0, int lane) {
    int row = r0 + ((lane >> 3) & 1) * 8 + (lane & 7);
    return SWB((uint32_t)(row * 32 + (lane >> 4) * 16));
}
__device__ __forceinline__ uint32_t b_off(int c0, int lane) {
    int row = c0 + ((lane >> 4) << 3) + (lane & 7);
    return SWB((uint32_t)(row * 32 + ((lane >> 3) & 1) * 16));
}

// ---------------------------------------------------------------------------
// 4. gemm1 (fp16 m16n8k16 + ldmatrix): h = silu(X@W1^T) * (X@W3^T)
//    CTA 64x128, warps 2Mx4N (32x32), BK=16, 4-stage cp.async, 1 sync/kt
// ---------------------------------------------------------------------------
__global__ __launch_bounds__(256, 2) void gemm1_tc() {
    int e     = blockIdx.z;
    int off   = g_off[e];
    int count = g_off[e + 1] - off;
    int m0    = blockIdx.x * 64;
    if (m0 >= count) return;
    int n0 = blockIdx.y * 128;

    extern __shared__ __half smh[];
    __shared__ int toks[64];

    int tid = threadIdx.x, wid = tid >> 5, lane = tid & 31;
    int q = lane >> 2, tq = lane & 3;
    int wM = wid & 1, wN = wid >> 1;

    if (tid < 64) toks[tid] = g_slot_token[off + min(m0 + tid, count - 1)];
    __syncthreads();

    const __half* w1e = g_w1h + ((size_t)e * F + n0) * H;
    const __half* w3e = g_w3h + ((size_t)e * F + n0) * H;

    uint32_t sb0 = smem_u32(smh);
    int lrow = tid >> 1, lseg = tid & 1;
    uint32_t wdst = SWB((uint32_t)(lrow * 32 + lseg * 16));

    // per-thread ldmatrix offsets (region-relative)
    uint32_t aOf[2], b1Of[2], b3Of[2];
#pragma unroll
    for (int mt = 0; mt < 2; mt++) aOf[mt] = a_off(wM * 32 + mt * 16, lane);
#pragma unroll
    for (int p = 0; p < 2; p++) {
        b1Of[p] = 2048 + b_off(wN * 32 + p * 16, lane);
        b3Of[p] = 6144 + b_off(wN * 32 + p * 16, lane);
    }

    auto load_stage = [&](int kt, int buf) {
        uint32_t sb = sb0 + (uint32_t)buf * STG1B;
        int kf = kt * 16 + lseg * 8;
        if (tid < 128)
            cp_async16(sb + wdst, g_xh + (size_t)toks[lrow] * H + kf);
        cp_async16(sb + 2048 + wdst, w1e + (size_t)lrow * H + kf);
        cp_async16(sb + 6144 + wdst, w3e + (size_t)lrow * H + kf);
    };

    float acc1[2][4][4] = {}, acc3[2][4][4] = {};

    load_stage(0, 0); CP_COMMIT();
    load_stage(1, 1); CP_COMMIT();
    load_stage(2, 2); CP_COMMIT();

    const int NK = H / 16;   // 64
    for (int kt = 0; kt < NK; kt++) {
        CP_WAIT2();                               // stage kt complete
        __syncthreads();                          // all warps past kt-1 compute
        if (kt + 3 < NK) load_stage(kt + 3, (kt + 3) & 3);
        CP_COMMIT();

        uint32_t stb = sb0 + (uint32_t)(kt & 3) * STG1B;
        uint32_t a[2][4], f1[2][4], f3[2][4];
        ldsm4(a[0], stb + aOf[0]);
        ldsm4(a[1], stb + aOf[1]);
        ldsm4(f1[0], stb + b1Of[0]);
        ldsm4(f1[1], stb + b1Of[1]);
        ldsm4(f3[0], stb + b3Of[0]);
        ldsm4(f3[1], stb + b3Of[1]);
#pragma unroll
        for (int nt = 0; nt < 4; nt++) {
            int p = nt >> 1, s = (nt & 1) * 2;
#pragma unroll
            for (int mt = 0; mt < 2; mt++) {
                mma16(acc1[mt][nt], a[mt], f1[p][s], f1[p][s + 1]);
                mma16(acc3[mt][nt], a[mt], f3[p][s], f3[p][s + 1]);
            }
        }
    }

    // epilogue: SwiGLU -> g_hh fp16 (canonical layout)
#pragma unroll
    for (int mt = 0; mt < 2; mt++) {
#pragma unroll
        for (int hf = 0; hf < 2; hf++) {
            int m = m0 + wM * 32 + mt * 16 + q + hf * 8;
            if (m >= count) continue;
            __half* hrow = g_hh + (size_t)(off + m) * F + n0 + wN * 32;
#pragma unroll
            for (int nt = 0; nt < 4; nt++) {
                float g0 = acc1[mt][nt][hf * 2 + 0];
                float g1 = acc1[mt][nt][hf * 2 + 1];
                float u0 = acc3[mt][nt][hf * 2 + 0];
                float u1 = acc3[mt][nt][hf * 2 + 1];
                float h0 = (g0 / (1.f + expf(-g0))) * u0;
                float h1 = (g1 / (1.f + expf(-g1))) * u1;
                *(__half2*)(hrow + nt * 8 + 2 * tq) = __floats2half2_rn(h0, h1);
            }
        }
    }
}

// ---------------------------------------------------------------------------
// 5. gemm2 (fp16 m16n8k16 + ldmatrix): y = c * (h @ W2^T), fp16 output
// ---------------------------------------------------------------------------
__global__ __launch_bounds__(256, 2) void gemm2_tc() {
    int e     = blockIdx.z;
    int off   = g_off[e];
    int count = g_off[e + 1] - off;
    int m0    = blockIdx.x * 64;
    if (m0 >= count) return;
    int n0 = blockIdx.y * 128;

    extern __shared__ __half smh[];

    int tid = threadIdx.x, wid = tid >> 5, lane = tid & 31;
    int q = lane >> 2, tq = lane & 3;
    int wM = wid & 1, wN = wid >> 1;

    const __half* w2e = g_w2h + ((size_t)e * H + n0) * F;
    int cm1 = count - 1;

    uint32_t sb0 = smem_u32(smh);
    int lrow = tid >> 1, lseg = tid & 1;
    uint32_t wdst = SWB((uint32_t)(lrow * 32 + lseg * 16));
    int arow = off + min(m0 + lrow, cm1);

    uint32_t aOf[2], bOf[2];
#pragma unroll
    for (int mt = 0; mt < 2; mt++) aOf[mt] = a_off(wM * 32 + mt * 16, lane);
#pragma unroll
    for (int p = 0; p < 2; p++) bOf[p] = 2048 + b_off(wN * 32 + p * 16, lane);

    auto load_stage = [&](int kt, int buf) {
        uint32_t sb = sb0 + (uint32_t)buf * STG2B;
        int kf = kt * 16 + lseg * 8;
        if (tid < 128)
            cp_async16(sb + wdst, g_hh + (size_t)arow * F + kf);
        cp_async16(sb + 2048 + wdst, w2e + (size_t)lrow * F + kf);
    };

    float acc[2][4][4] = {};

    load_stage(0, 0); CP_COMMIT();
    load_stage(1, 1); CP_COMMIT();
    load_stage(2, 2); CP_COMMIT();

    const int NK = F / 16;   // 32
    for (int kt = 0; kt < NK; kt++) {
        CP_WAIT2();
        __syncthreads();
        if (kt + 3 < NK) load_stage(kt + 3, (kt + 3) & 3);
        CP_COMMIT();

        uint32_t stb = sb0 + (uint32_t)(kt & 3) * STG2B;
        uint32_t a[2][4], fb[2][4];
        ldsm4(a[0], stb + aOf[0]);
        ldsm4(a[1], stb + aOf[1]);
        ldsm4(fb[0], stb + bOf[0]);
        ldsm4(fb[1], stb + bOf[1]);
#pragma unroll
        for (int nt = 0; nt < 4; nt++) {
            int p = nt >> 1, s = (nt & 1) * 2;
#pragma unroll
            for (int mt = 0; mt < 2; mt++)
                mma16(acc[mt][nt], a[mt], fb[p][s], fb[p][s + 1]);
        }
    }

    // epilogue: scale by combine weight, store g_yh fp16
#pragma unroll
    for (int mt = 0; mt < 2; mt++) {
#pragma unroll
        for (int hf = 0; hf < 2; hf++) {
            int m = m0 + wM * 32 + mt * 16 + q + hf * 8;
            if (m >= count) continue;
            float cw = g_slot_w[off + m];
            __half* yrow = g_yh + (size_t)(off + m) * H + n0 + wN * 32;
#pragma unroll
            for (int nt = 0; nt < 4; nt++) {
                float o0 = cw * acc[mt][nt][hf * 2 + 0];
                float o1 = cw * acc[mt][nt][hf * 2 + 1];
                *(__half2*)(yrow + nt * 8 + 2 * tq) = __floats2half2_rn(o0, o1);
            }
        }
    }
}

// ---------------------------------------------------------------------------
// 6. combine: out[t] = sum of the token's K slot rows (fixed order, fp32 acc)
// ---------------------------------------------------------------------------
__global__ void combine_kernel(float* __restrict__ out) {
    int t = blockIdx.x;
    const uint4* r0 = (const uint4*)(g_yh + (size_t)g_token_slot[t * K + 0] * H);
    const uint4* r1 = (const uint4*)(g_yh + (size_t)g_token_slot[t * K + 1] * H);
    const uint4* r2 = (const uint4*)(g_yh + (size_t)g_token_slot[t * K + 2] * H);
    const uint4* r3 = (const uint4*)(g_yh + (size_t)g_token_slot[t * K + 3] * H);
    float4* o = (float4*)(out + (size_t)t * H);
    int i = threadIdx.x;   // 128 threads x 8 halves = 1024 = H
    uint4 a = r0[i], b = r1[i], c = r2[i], d = r3[i];
    const __half2* ah = (const __half2*)&a;
    const __half2* bh = (const __half2*)&b;
    const __half2* ch = (const __half2*)&c;
    const __half2* dh = (const __half2*)&d;
    float4 v0, v1;
    float* vp = &v0.x;
#pragma unroll
    for (int j = 0; j < 4; j++) {
        float2 fa = __half22float2(ah[j]), fb = __half22float2(bh[j]);
        float2 fc = __half22float2(ch[j]), fd = __half22float2(dh[j]);
        vp[2 * j + 0] = fa.x + fb.x + fc.x + fd.x;
        vp[2 * j + 1] = fa.y + fb.y + fc.y + fd.y;
    }
    (void)v1;
    o[2 * i + 0] = v0;
    // second half written via vp offset trick is fragile; do explicitly:
    // (vp covers only v0; recompute for upper 4 halves)
    // NOTE: loop above wrote 8 floats into v0..v1 contiguously only if
    // compiler keeps them adjacent — instead write directly:
}

// safer combine (replaces the above at call site)
__global__ void combine_kernel2(float* __restrict__ out) {
    int t = blockIdx.x;
    const __half* y0 = g_yh + (size_t)g_token_slot[t * K + 0] * H;
    const __half* y1 = g_yh + (size_t)g_token_slot[t * K + 1] * H;
    const __half* y2 = g_yh + (size_t)g_token_slot[t * K + 2] * H;
    const __half* y3 = g_yh + (size_t)g_token_slot[t * K + 3] * H;
    float* orow = out + (size_t)t * H;
    int i = threadIdx.x;               // 256 threads x 4 halves
    for (int c = i * 4; c < H; c += blockDim.x * 4) {
        uint2 a = *(const uint2*)(y0 + c), b = *(const uint2*)(y1 + c);
        uint2 cc = *(const uint2*)(y2 + c), d = *(const uint2*)(y3 + c);
        const __half2* ah = (const __half2*)&a;
        const __half2* bh = (const __half2*)&b;
        const __half2* ch = (const __half2*)&cc;
        const __half2* dh = (const __half2*)&d;
        float4 v;
        float2 s0, s1;
        s0.x = __low2float(ah[0])  + __low2float(bh[0])  + __low2float(ch[0])  + __low2float(dh[0]);
        s0.y = __high2float(ah[0]) + __high2float(bh[0]) + __high2float(ch[0]) + __high2float(dh[0]);
        s1.x = __low2float(ah[1])  + __low2float(bh[1])  + __low2float(ch[1])  + __low2float(dh[1]);
        s1.y = __high2float(ah[1]) + __high2float(bh[1]) + __high2float(ch[1]) + __high2float(dh[1]);
        v.x = s0.x; v.y = s0.y; v.z = s1.x; v.w = s1.y;
        *(float4*)(orow + c) = v;
    }
}

// ---------------------------------------------------------------------------
extern "C" void kernel_launch(void* const* d_in, const int* in_sizes, int n_in,
                              void* d_out, int out_size) {
    const float* x    = (const float*)d_in[0];
    const float* gw   = (const float*)d_in[1];
    const float* bias = (const float*)d_in[2];
    const float* w1   = (const float*)d_in[3];
    const float* w3   = (const float*)d_in[4];
    const float* w2   = (const float*)d_in[5];
    float* out = (float*)d_out;

    const int SM1 = 4 * STG1B;   // 40960 B
    const int SM2 = 4 * STG2B;   // 24576 B
    cudaFuncSetAttribute(gemm1_tc, cudaFuncAttributeMaxDynamicSharedMemorySize, SM1);
    cudaFuncSetAttribute(gemm2_tc, cudaFuncAttributeMaxDynamicSharedMemorySize, SM2);

    prep_kernel<<<1024, 256>>>((const float4*)x, (const float4*)w1,
                               (const float4*)w3, (const float4*)w2);
    router_kernel<<<(T * 32 + 255) / 256, 256>>>(x, gw, bias);
    scan_kernel<<<1, 1>>>();
    scatter_kernel<<<(S + 255) / 256, 256>>>();

    gemm1_tc<<<dim3(T / 64, F / 128, E), 256, SM1>>>();
    gemm2_tc<<<dim3(T / 64, H / 128, E), 256, SM2>>>();

    combine_kernel2<<<T, 256>>>(out);
}

// round 10
// speedup vs baseline: 7.2093x; 1.1945x over previous
#include <cuda_runtime.h>
#include <cuda_fp16.h>
#include <cstdint>
#include <math.h>

#define T 4096
#define H 1024
#define F 512
#define E 16
#define K 4
#define S (T*K)
#define SP ((size_t)E * T)          // padded slot space (per-expert regions)

// ---------------- scratch (device globals; no runtime allocation) ----------
__device__ int    g_counts[E];
__device__ int    g_slot_token[SP];
__device__ float  g_slot_w[SP];
__device__ int    g_token_slot[S];
// fp16 (RN) operands / activations / outputs
__device__ __align__(256) __half g_xh [(size_t)T * H];
__device__ __align__(256) __half g_w1h[(size_t)E * F * H];
__device__ __align__(256) __half g_w3h[(size_t)E * F * H];
__device__ __align__(256) __half g_w2h[(size_t)E * H * F];
__device__ __align__(256) __half g_hh [SP * F];
__device__ __align__(256) __half g_yh [SP * H];

// ---------------- helpers ---------------------------------------------------
__device__ __forceinline__ void mma16(float* d, const uint32_t* a,
                                      uint32_t b0, uint32_t b1) {
    asm volatile(
        "mma.sync.aligned.m16n8k16.row.col.f32.f16.f16.f32 "
        "{%0,%1,%2,%3}, {%4,%5,%6,%7}, {%8,%9}, {%0,%1,%2,%3};"
        : "+f"(d[0]), "+f"(d[1]), "+f"(d[2]), "+f"(d[3])
        : "r"(a[0]), "r"(a[1]), "r"(a[2]), "r"(a[3]), "r"(b0), "r"(b1));
}
__device__ __forceinline__ void ldsm4(uint32_t* r, uint32_t addr) {
    asm volatile(
        "ldmatrix.sync.aligned.m8n8.x4.shared.b16 {%0,%1,%2,%3}, [%4];"
        : "=r"(r[0]), "=r"(r[1]), "=r"(r[2]), "=r"(r[3]) : "r"(addr));
}
__device__ __forceinline__ uint32_t smem_u32(const void* p) {
    uint32_t a;
    asm("{ .reg .u64 t; cvta.to.shared.u64 t, %1; cvt.u32.u64 %0, t; }"
        : "=r"(a) : "l"(p));
    return a;
}
__device__ __forceinline__ void cp_async16(uint32_t dst, const void* src) {
    asm volatile("cp.async.cg.shared.global [%0], [%1], 16;" :: "r"(dst), "l"(src));
}
#define CP_COMMIT() asm volatile("cp.async.commit_group;" ::: "memory")
#define CP_WAIT2()  asm volatile("cp.async.wait_group 2;" ::: "memory")

// 64B-row swizzle: XOR row bits (b>>7) into 16B-column bits [4:6).
// NOTE: for the ks=1 (k+8..k+15 within 32B) fragment, the unswizzled column
// base has bit5 clear, so SWB64(base+32) == SWB64(base) ^ 32 — the ks offset
// must be applied with XOR, never ADD (ADD can carry into the row bits).
#define SWB64(b) ((b) ^ (((((uint32_t)(b)) >> 7) & 3) << 4))

#define STG1B 20480     // x 4KB + w1 8KB + w3 8KB  (64B rows, BK=32 halves)
#define STG2B 12288     // h 4KB + w2 8KB

// ---------------------------------------------------------------------------
// 0. prepass: fp32 -> fp16 (RN), plain layout. Also zeroes g_counts.
// ---------------------------------------------------------------------------
__device__ __forceinline__ void conv8(const float4* __restrict__ src,
                                      uint4* __restrict__ dst, size_t i) {
    float4 f0 = src[2 * i], f1 = src[2 * i + 1];
    __half2 h0 = __floats2half2_rn(f0.x, f0.y), h1 = __floats2half2_rn(f0.z, f0.w);
    __half2 h2 = __floats2half2_rn(f1.x, f1.y), h3 = __floats2half2_rn(f1.z, f1.w);
    uint4 o;
    o.x = *(uint32_t*)&h0; o.y = *(uint32_t*)&h1;
    o.z = *(uint32_t*)&h2; o.w = *(uint32_t*)&h3;
    dst[i] = o;
}
__global__ void prep_kernel(const float4* __restrict__ x,
                            const float4* __restrict__ w1,
                            const float4* __restrict__ w3,
                            const float4* __restrict__ w2) {
    if (blockIdx.x == 0 && threadIdx.x < E) g_counts[threadIdx.x] = 0;
    size_t i0 = blockIdx.x * blockDim.x + threadIdx.x;
    size_t stride = (size_t)gridDim.x * blockDim.x;
    const size_t nx = (size_t)T * H / 8, nw = (size_t)E * F * H / 8;
    for (size_t i = i0; i < nx; i += stride) conv8(x,  (uint4*)g_xh,  i);
    for (size_t i = i0; i < nw; i += stride) conv8(w1, (uint4*)g_w1h, i);
    for (size_t i = i0; i < nw; i += stride) conv8(w3, (uint4*)g_w3h, i);
    for (size_t i = i0; i < nw; i += stride) conv8(w2, (uint4*)g_w2h, i);
}

// ---------------------------------------------------------------------------
// 1. router (exact fp32) — also does slot assignment (no scan/scatter needed:
//    expert e owns padded region [e*T, e*T+count), order within is arbitrary)
// ---------------------------------------------------------------------------
__global__ void router_kernel(const float* __restrict__ x,
                              const float* __restrict__ gw,
                              const float* __restrict__ bias) {
    int warp = (blockIdx.x * blockDim.x + threadIdx.x) >> 5;
    int lane = threadIdx.x & 31;
    if (warp >= T) return;

    const float* xr = x + (size_t)warp * H;
    float acc[E];
#pragma unroll
    for (int e = 0; e < E; e++) acc[e] = 0.f;
    for (int h = lane; h < H; h += 32) {
        float xv = xr[h];
#pragma unroll
        for (int e = 0; e < E; e++)
            acc[e] = fmaf(xv, __ldg(&gw[e * H + h]), acc[e]);
    }
#pragma unroll
    for (int o = 16; o > 0; o >>= 1)
#pragma unroll
        for (int e = 0; e < E; e++)
            acc[e] += __shfl_xor_sync(0xffffffffu, acc[e], o);

    if (lane == 0) {
        float sc[E], sel[E];
#pragma unroll
        for (int e = 0; e < E; e++) {
            sc[e]  = 1.f / (1.f + expf(-acc[e]));
            sel[e] = sc[e] + bias[e];
        }
        bool used[E];
#pragma unroll
        for (int e = 0; e < E; e++) used[e] = false;
        float sum = 0.f;
        int   idx[K]; float w[K];
#pragma unroll
        for (int k = 0; k < K; k++) {
            float best = -1e30f; int bi = 0;
            for (int e = 0; e < E; e++)
                if (!used[e] && sel[e] > best) { best = sel[e]; bi = e; }
            used[bi] = true; idx[k] = bi; w[k] = sc[bi]; sum += sc[bi];
        }
        float inv = 1.f / sum;
#pragma unroll
        for (int k = 0; k < K; k++) {
            int e   = idx[k];
            int pos = e * T + atomicAdd(&g_counts[e], 1);
            g_slot_token[pos]        = warp;
            g_slot_w[pos]            = w[k] * inv;
            g_token_slot[warp*K + k] = pos;
        }
    }
}

// ---------------------------------------------------------------------------
// ldmatrix address offsets (region-relative, 64B rows, ks=0; ks=1 -> XOR 32)
// ---------------------------------------------------------------------------
__device__ __forceinline__ uint32_t a_off64(int r0, int lane) {
    int row = r0 + ((lane >> 3) & 1) * 8 + (lane & 7);
    return SWB64((uint32_t)(row * 64 + (lane >> 4) * 16));
}
__device__ __forceinline__ uint32_t b_off64(int c0, int lane) {
    int row = c0 + ((lane >> 4) << 3) + (lane & 7);
    return SWB64((uint32_t)(row * 64 + ((lane >> 3) & 1) * 16));
}

// ---------------------------------------------------------------------------
// 2. gemm1 (fp16 m16n8k16 + ldmatrix): h = silu(X@W1^T) * (X@W3^T)
//    CTA 64x128, warps 2Mx4N (32x32), BK=32, 4-stage cp.async, 1 sync / 32 mma
// ---------------------------------------------------------------------------
__global__ __launch_bounds__(256, 2) void gemm1_tc() {
    int e     = blockIdx.z;
    int off   = e * T;
    int count = g_counts[e];
    int m0    = blockIdx.x * 64;
    if (m0 >= count) return;
    int n0 = blockIdx.y * 128;

    extern __shared__ __half smh[];
    __shared__ int toks[64];

    int tid = threadIdx.x, wid = tid >> 5, lane = tid & 31;
    int q = lane >> 2, tq = lane & 3;
    int wM = wid & 1, wN = wid >> 1;

    if (tid < 64) toks[tid] = g_slot_token[off + min(m0 + tid, count - 1)];
    __syncthreads();

    const __half* w1e = g_w1h + ((size_t)e * F + n0) * H;
    const __half* w3e = g_w3h + ((size_t)e * F + n0) * H;

    uint32_t sb0 = smem_u32(smh);
    int lrow = tid >> 2, lseg = tid & 3;                 // 64B rows, 4x16B segs
    uint32_t wdstA  = SWB64((uint32_t)(lrow * 64 + lseg * 16));
    uint32_t wdstW2 = SWB64((uint32_t)((64 + lrow) * 64 + lseg * 16));

    uint32_t aOf[2], b1Of[2], b3Of[2];
#pragma unroll
    for (int mt = 0; mt < 2; mt++) aOf[mt] = a_off64(wM * 32 + mt * 16, lane);
#pragma unroll
    for (int p = 0; p < 2; p++) {
        b1Of[p] = 4096  + b_off64(wN * 32 + p * 16, lane);
        b3Of[p] = 12288 + b_off64(wN * 32 + p * 16, lane);
    }

    auto load_stage = [&](int kt, int buf) {
        uint32_t sb = sb0 + (uint32_t)buf * STG1B;
        int kf = kt * 32 + lseg * 8;
        cp_async16(sb + wdstA, g_xh + (size_t)toks[lrow] * H + kf);
        cp_async16(sb + 4096  + wdstA,  w1e + (size_t)lrow        * H + kf);
        cp_async16(sb + 4096  + wdstW2, w1e + (size_t)(64 + lrow) * H + kf);
        cp_async16(sb + 12288 + wdstA,  w3e + (size_t)lrow        * H + kf);
        cp_async16(sb + 12288 + wdstW2, w3e + (size_t)(64 + lrow) * H + kf);
    };

    float acc1[2][4][4] = {}, acc3[2][4][4] = {};

    load_stage(0, 0); CP_COMMIT();
    load_stage(1, 1); CP_COMMIT();
    load_stage(2, 2); CP_COMMIT();

    const int NK = H / 32;   // 32
    for (int kt = 0; kt < NK; kt++) {
        CP_WAIT2();                               // stage kt resident
        __syncthreads();                          // all warps done with kt-1
        if (kt + 3 < NK) load_stage(kt + 3, (kt + 3) & 3);
        CP_COMMIT();

        uint32_t stb = sb0 + (uint32_t)(kt & 3) * STG1B;
#pragma unroll
        for (int ks = 0; ks < 2; ks++) {
            uint32_t kx = ks * 32;                // XOR offset (NOT add!)
            uint32_t a[2][4], f1[2][4], f3[2][4];
            ldsm4(a[0],  stb + (aOf[0]  ^ kx));
            ldsm4(a[1],  stb + (aOf[1]  ^ kx));
            ldsm4(f1[0], stb + (b1Of[0] ^ kx));
            ldsm4(f1[1], stb + (b1Of[1] ^ kx));
            ldsm4(f3[0], stb + (b3Of[0] ^ kx));
            ldsm4(f3[1], stb + (b3Of[1] ^ kx));
#pragma unroll
            for (int nt = 0; nt < 4; nt++) {
                int p = nt >> 1, s = (nt & 1) * 2;
#pragma unroll
                for (int mt = 0; mt < 2; mt++) {
                    mma16(acc1[mt][nt], a[mt], f1[p][s], f1[p][s + 1]);
                    mma16(acc3[mt][nt], a[mt], f3[p][s], f3[p][s + 1]);
                }
            }
        }
    }

    // epilogue: SwiGLU -> g_hh fp16
#pragma unroll
    for (int mt = 0; mt < 2; mt++) {
#pragma unroll
        for (int hf = 0; hf < 2; hf++) {
            int m = m0 + wM * 32 + mt * 16 + q + hf * 8;
            if (m >= count) continue;
            __half* hrow = g_hh + (size_t)(off + m) * F + n0 + wN * 32;
#pragma unroll
            for (int nt = 0; nt < 4; nt++) {
                float g0 = acc1[mt][nt][hf * 2 + 0];
                float g1 = acc1[mt][nt][hf * 2 + 1];
                float u0 = acc3[mt][nt][hf * 2 + 0];
                float u1 = acc3[mt][nt][hf * 2 + 1];
                float h0 = (g0 / (1.f + expf(-g0))) * u0;
                float h1 = (g1 / (1.f + expf(-g1))) * u1;
                *(__half2*)(hrow + nt * 8 + 2 * tq) = __floats2half2_rn(h0, h1);
            }
        }
    }
}

// ---------------------------------------------------------------------------
// 3. gemm2 (fp16 m16n8k16 + ldmatrix): y = c * (h @ W2^T), fp16 output
//    BK=32, NK = F/32 = 16
// ---------------------------------------------------------------------------
__global__ __launch_bounds__(256, 2) void gemm2_tc() {
    int e     = blockIdx.z;
    int off   = e * T;
    int count = g_counts[e];
    int m0    = blockIdx.x * 64;
    if (m0 >= count) return;
    int n0 = blockIdx.y * 128;

    extern __shared__ __half smh[];

    int tid = threadIdx.x, wid = tid >> 5, lane = tid & 31;
    int q = lane >> 2, tq = lane & 3;
    int wM = wid & 1, wN = wid >> 1;

    const __half* w2e = g_w2h + ((size_t)e * H + n0) * F;
    int cm1 = count - 1;

    uint32_t sb0 = smem_u32(smh);
    int lrow = tid >> 2, lseg = tid & 3;
    uint32_t wdstA  = SWB64((uint32_t)(lrow * 64 + lseg * 16));
    uint32_t wdstW2 = SWB64((uint32_t)((64 + lrow) * 64 + lseg * 16));
    int arow = off + min(m0 + lrow, cm1);

    uint32_t aOf[2], bOf[2];
#pragma unroll
    for (int mt = 0; mt < 2; mt++) aOf[mt] = a_off64(wM * 32 + mt * 16, lane);
#pragma unroll
    for (int p = 0; p < 2; p++) bOf[p] = 4096 + b_off64(wN * 32 + p * 16, lane);

    auto load_stage = [&](int kt, int buf) {
        uint32_t sb = sb0 + (uint32_t)buf * STG2B;
        int kf = kt * 32 + lseg * 8;
        cp_async16(sb + wdstA, g_hh + (size_t)arow * F + kf);
        cp_async16(sb + 4096 + wdstA,  w2e + (size_t)lrow        * F + kf);
        cp_async16(sb + 4096 + wdstW2, w2e + (size_t)(64 + lrow) * F + kf);
    };

    float acc[2][4][4] = {};

    load_stage(0, 0); CP_COMMIT();
    load_stage(1, 1); CP_COMMIT();
    load_stage(2, 2); CP_COMMIT();

    const int NK = F / 32;   // 16
    for (int kt = 0; kt < NK; kt++) {
        CP_WAIT2();
        __syncthreads();
        if (kt + 3 < NK) load_stage(kt + 3, (kt + 3) & 3);
        CP_COMMIT();

        uint32_t stb = sb0 + (uint32_t)(kt & 3) * STG2B;
#pragma unroll
        for (int ks = 0; ks < 2; ks++) {
            uint32_t kx = ks * 32;                // XOR offset (NOT add!)
            uint32_t a[2][4], fb[2][4];
            ldsm4(a[0],  stb + (aOf[0] ^ kx));
            ldsm4(a[1],  stb + (aOf[1] ^ kx));
            ldsm4(fb[0], stb + (bOf[0] ^ kx));
            ldsm4(fb[1], stb + (bOf[1] ^ kx));
#pragma unroll
            for (int nt = 0; nt < 4; nt++) {
                int p = nt >> 1, s = (nt & 1) * 2;
#pragma unroll
                for (int mt = 0; mt < 2; mt++)
                    mma16(acc[mt][nt], a[mt], fb[p][s], fb[p][s + 1]);
            }
        }
    }

    // epilogue: scale by combine weight, store g_yh fp16
#pragma unroll
    for (int mt = 0; mt < 2; mt++) {
#pragma unroll
        for (int hf = 0; hf < 2; hf++) {
            int m = m0 + wM * 32 + mt * 16 + q + hf * 8;
            if (m >= count) continue;
            float cw = g_slot_w[off + m];
            __half* yrow = g_yh + (size_t)(off + m) * H + n0 + wN * 32;
#pragma unroll
            for (int nt = 0; nt < 4; nt++) {
                float o0 = cw * acc[mt][nt][hf * 2 + 0];
                float o1 = cw * acc[mt][nt][hf * 2 + 1];
                *(__half2*)(yrow + nt * 8 + 2 * tq) = __floats2half2_rn(o0, o1);
            }
        }
    }
}

// ---------------------------------------------------------------------------
// 4. combine: out[t] = sum of the token's K slot rows (fixed order, fp32 acc)
// ---------------------------------------------------------------------------
__global__ void combine_kernel(float* __restrict__ out) {
    int t = blockIdx.x;
    const __half* y0 = g_yh + (size_t)g_token_slot[t * K + 0] * H;
    const __half* y1 = g_yh + (size_t)g_token_slot[t * K + 1] * H;
    const __half* y2 = g_yh + (size_t)g_token_slot[t * K + 2] * H;
    const __half* y3 = g_yh + (size_t)g_token_slot[t * K + 3] * H;
    float* orow = out + (size_t)t * H;
    for (int c = threadIdx.x * 4; c < H; c += blockDim.x * 4) {
        uint2 a = *(const uint2*)(y0 + c), b = *(const uint2*)(y1 + c);
        uint2 cc = *(const uint2*)(y2 + c), d = *(const uint2*)(y3 + c);
        const __half2* ah = (const __half2*)&a;
        const __half2* bh = (const __half2*)&b;
        const __half2* ch = (const __half2*)&cc;
        const __half2* dh = (const __half2*)&d;
        float4 v;
        v.x = __low2float(ah[0])  + __low2float(bh[0])  + __low2float(ch[0])  + __low2float(dh[0]);
        v.y = __high2float(ah[0]) + __high2float(bh[0]) + __high2float(ch[0]) + __high2float(dh[0]);
        v.z = __low2float(ah[1])  + __low2float(bh[1])  + __low2float(ch[1])  + __low2float(dh[1]);
        v.w = __high2float(ah[1]) + __high2float(bh[1]) + __high2float(ch[1]) + __high2float(dh[1]);
        *(float4*)(orow + c) = v;
    }
}

// ---------------------------------------------------------------------------
extern "C" void kernel_launch(void* const* d_in, const int* in_sizes, int n_in,
                              void* d_out, int out_size) {
    const float* x    = (const float*)d_in[0];
    const float* gw   = (const float*)d_in[1];
    const float* bias = (const float*)d_in[2];
    const float* w1   = (const float*)d_in[3];
    const float* w3   = (const float*)d_in[4];
    const float* w2   = (const float*)d_in[5];
    float* out = (float*)d_out;

    const int SM1 = 4 * STG1B;   // 81920 B
    const int SM2 = 4 * STG2B;   // 49152 B
    cudaFuncSetAttribute(gemm1_tc, cudaFuncAttributeMaxDynamicSharedMemorySize, SM1);
    cudaFuncSetAttribute(gemm2_tc, cudaFuncAttributeMaxDynamicSharedMemorySize, SM2);

    prep_kernel<<<1024, 256>>>((const float4*)x, (const float4*)w1,
                               (const float4*)w3, (const float4*)w2);
    router_kernel<<<(T * 32 + 255) / 256, 256>>>(x, gw, bias);

    gemm1_tc<<<dim3(T / 64, F / 128, E), 256, SM1>>>();
    gemm2_tc<<<dim3(T / 64, H / 128, E), 256, SM2>>>();

    combine_kernel<<<T, 256>>>(out);
}

// round 11
// speedup vs baseline: 8.0607x; 1.1181x over previous
#include <cuda_runtime.h>
#include <cuda_fp16.h>
#include <cstdint>
#include <math.h>

#define T 4096
#define H 1024
#define F 512
#define E 16
#define K 4
#define S (T*K)
#define SP ((size_t)E * T)          // padded slot space (per-expert regions)

// ---------------- scratch (device globals; no runtime allocation) ----------
__device__ int    g_counts[E];      // zero-init at load; re-zeroed by combine
__device__ int    g_slot_token[SP];
__device__ float  g_slot_w[SP];
__device__ int    g_token_slot[S];
// fp16 (RN) operands / activations / outputs
__device__ __align__(256) __half g_xh [(size_t)T * H];
__device__ __align__(256) __half g_w1h[(size_t)E * F * H];
__device__ __align__(256) __half g_w3h[(size_t)E * F * H];
__device__ __align__(256) __half g_w2h[(size_t)E * H * F];
__device__ __align__(256) __half g_hh [SP * F];
__device__ __align__(256) __half g_yh [SP * H];

// ---------------- helpers ---------------------------------------------------
__device__ __forceinline__ void mma16(float* d, const uint32_t* a,
                                      uint32_t b0, uint32_t b1) {
    asm volatile(
        "mma.sync.aligned.m16n8k16.row.col.f32.f16.f16.f32 "
        "{%0,%1,%2,%3}, {%4,%5,%6,%7}, {%8,%9}, {%0,%1,%2,%3};"
        : "+f"(d[0]), "+f"(d[1]), "+f"(d[2]), "+f"(d[3])
        : "r"(a[0]), "r"(a[1]), "r"(a[2]), "r"(a[3]), "r"(b0), "r"(b1));
}
__device__ __forceinline__ void ldsm4(uint32_t* r, uint32_t addr) {
    asm volatile(
        "ldmatrix.sync.aligned.m8n8.x4.shared.b16 {%0,%1,%2,%3}, [%4];"
        : "=r"(r[0]), "=r"(r[1]), "=r"(r[2]), "=r"(r[3]) : "r"(addr));
}
__device__ __forceinline__ uint32_t smem_u32(const void* p) {
    uint32_t a;
    asm("{ .reg .u64 t; cvta.to.shared.u64 t, %1; cvt.u32.u64 %0, t; }"
        : "=r"(a) : "l"(p));
    return a;
}
__device__ __forceinline__ void cp_async16(uint32_t dst, const void* src) {
    asm volatile("cp.async.cg.shared.global [%0], [%1], 16;" :: "r"(dst), "l"(src));
}
#define CP_COMMIT() asm volatile("cp.async.commit_group;" ::: "memory")
#define CP_WAIT2()  asm volatile("cp.async.wait_group 2;" ::: "memory")

// 64B-row swizzle: XOR row bits (b>>7) into 16B-column bits [4:6).
// ks=1 fragment offset must be applied with XOR 32 (never ADD — carry would
// corrupt the row bits).
#define SWB64(b) ((b) ^ (((((uint32_t)(b)) >> 7) & 3) << 4))

#define STG1B 20480     // gemm1: x 4KB + w1 8KB + w3 8KB (64B rows, BK=32)
#define STG2B 20480     // gemm2: h 4KB + w2 16KB (256 N-rows)

// ---------------------------------------------------------------------------
// 0. fused prep + router:
//    blocks [0, RB): router (exact fp32, writes slots; counts pre-zeroed by
//                    the PREVIOUS call's combine / static zero-init)
//    blocks [RB, RB+PB): fp32 -> fp16 (RN) conversion of x, w1, w3, w2
// ---------------------------------------------------------------------------
#define RB 512
#define PB 1024

__device__ __forceinline__ void conv8(const float4* __restrict__ src,
                                      uint4* __restrict__ dst, size_t i) {
    float4 f0 = src[2 * i], f1 = src[2 * i + 1];
    __half2 h0 = __floats2half2_rn(f0.x, f0.y), h1 = __floats2half2_rn(f0.z, f0.w);
    __half2 h2 = __floats2half2_rn(f1.x, f1.y), h3 = __floats2half2_rn(f1.z, f1.w);
    uint4 o;
    o.x = *(uint32_t*)&h0; o.y = *(uint32_t*)&h1;
    o.z = *(uint32_t*)&h2; o.w = *(uint32_t*)&h3;
    dst[i] = o;
}

__global__ void prep_router_kernel(const float* __restrict__ x,
                                   const float* __restrict__ gw,
                                   const float* __restrict__ bias,
                                   const float4* __restrict__ w1,
                                   const float4* __restrict__ w3,
                                   const float4* __restrict__ w2) {
    if (blockIdx.x >= RB) {
        // ---- prep part ----
        size_t i0 = (size_t)(blockIdx.x - RB) * blockDim.x + threadIdx.x;
        size_t stride = (size_t)PB * blockDim.x;
        const size_t nx = (size_t)T * H / 8, nw = (size_t)E * F * H / 8;
        const float4* x4 = (const float4*)x;
        for (size_t i = i0; i < nx; i += stride) conv8(x4, (uint4*)g_xh,  i);
        for (size_t i = i0; i < nw; i += stride) conv8(w1, (uint4*)g_w1h, i);
        for (size_t i = i0; i < nw; i += stride) conv8(w3, (uint4*)g_w3h, i);
        for (size_t i = i0; i < nw; i += stride) conv8(w2, (uint4*)g_w2h, i);
        return;
    }
    // ---- router part: one warp per token ----
    int warp = (blockIdx.x * blockDim.x + threadIdx.x) >> 5;
    int lane = threadIdx.x & 31;
    if (warp >= T) return;

    const float* xr = x + (size_t)warp * H;
    float acc[E];
#pragma unroll
    for (int e = 0; e < E; e++) acc[e] = 0.f;
    for (int h = lane; h < H; h += 32) {
        float xv = xr[h];
#pragma unroll
        for (int e = 0; e < E; e++)
            acc[e] = fmaf(xv, __ldg(&gw[e * H + h]), acc[e]);
    }
#pragma unroll
    for (int o = 16; o > 0; o >>= 1)
#pragma unroll
        for (int e = 0; e < E; e++)
            acc[e] += __shfl_xor_sync(0xffffffffu, acc[e], o);

    if (lane == 0) {
        float sc[E], sel[E];
#pragma unroll
        for (int e = 0; e < E; e++) {
            sc[e]  = 1.f / (1.f + expf(-acc[e]));
            sel[e] = sc[e] + bias[e];
        }
        bool used[E];
#pragma unroll
        for (int e = 0; e < E; e++) used[e] = false;
        float sum = 0.f;
        int   idx[K]; float w[K];
#pragma unroll
        for (int k = 0; k < K; k++) {
            float best = -1e30f; int bi = 0;
            for (int e = 0; e < E; e++)
                if (!used[e] && sel[e] > best) { best = sel[e]; bi = e; }
            used[bi] = true; idx[k] = bi; w[k] = sc[bi]; sum += sc[bi];
        }
        float inv = 1.f / sum;
#pragma unroll
        for (int k = 0; k < K; k++) {
            int e   = idx[k];
            int pos = e * T + atomicAdd(&g_counts[e], 1);
            g_slot_token[pos]        = warp;
            g_slot_w[pos]            = w[k] * inv;
            g_token_slot[warp*K + k] = pos;
        }
    }
}

// ---------------------------------------------------------------------------
// ldmatrix address offsets (region-relative, 64B rows, ks=0; ks=1 -> XOR 32)
// ---------------------------------------------------------------------------
__device__ __forceinline__ uint32_t a_off64(int r0, int lane) {
    int row = r0 + ((lane >> 3) & 1) * 8 + (lane & 7);
    return SWB64((uint32_t)(row * 64 + (lane >> 4) * 16));
}
__device__ __forceinline__ uint32_t b_off64(int c0, int lane) {
    int row = c0 + ((lane >> 4) << 3) + (lane & 7);
    return SWB64((uint32_t)(row * 64 + ((lane >> 3) & 1) * 16));
}

// ---------------------------------------------------------------------------
// 1. gemm1 (fp16 m16n8k16 + ldmatrix): h = silu(X@W1^T) * (X@W3^T)
//    CTA 64x128, warps 2Mx4N (32x32 x2 gemms), BK=32, 4-stage cp.async
// ---------------------------------------------------------------------------
__global__ __launch_bounds__(256, 2) void gemm1_tc() {
    int e     = blockIdx.z;
    int off   = e * T;
    int count = g_counts[e];
    int m0    = blockIdx.x * 64;
    if (m0 >= count) return;
    int n0 = blockIdx.y * 128;

    extern __shared__ __half smh[];
    __shared__ int toks[64];

    int tid = threadIdx.x, wid = tid >> 5, lane = tid & 31;
    int q = lane >> 2, tq = lane & 3;
    int wM = wid & 1, wN = wid >> 1;

    if (tid < 64) toks[tid] = g_slot_token[off + min(m0 + tid, count - 1)];
    __syncthreads();

    const __half* w1e = g_w1h + ((size_t)e * F + n0) * H;
    const __half* w3e = g_w3h + ((size_t)e * F + n0) * H;

    uint32_t sb0 = smem_u32(smh);
    int lrow = tid >> 2, lseg = tid & 3;
    uint32_t wdstA  = SWB64((uint32_t)(lrow * 64 + lseg * 16));
    uint32_t wdstW2 = SWB64((uint32_t)((64 + lrow) * 64 + lseg * 16));

    uint32_t aOf[2], b1Of[2], b3Of[2];
#pragma unroll
    for (int mt = 0; mt < 2; mt++) aOf[mt] = a_off64(wM * 32 + mt * 16, lane);
#pragma unroll
    for (int p = 0; p < 2; p++) {
        b1Of[p] = 4096  + b_off64(wN * 32 + p * 16, lane);
        b3Of[p] = 12288 + b_off64(wN * 32 + p * 16, lane);
    }

    auto load_stage = [&](int kt, int buf) {
        uint32_t sb = sb0 + (uint32_t)buf * STG1B;
        int kf = kt * 32 + lseg * 8;
        cp_async16(sb + wdstA, g_xh + (size_t)toks[lrow] * H + kf);
        cp_async16(sb + 4096  + wdstA,  w1e + (size_t)lrow        * H + kf);
        cp_async16(sb + 4096  + wdstW2, w1e + (size_t)(64 + lrow) * H + kf);
        cp_async16(sb + 12288 + wdstA,  w3e + (size_t)lrow        * H + kf);
        cp_async16(sb + 12288 + wdstW2, w3e + (size_t)(64 + lrow) * H + kf);
    };

    float acc1[2][4][4] = {}, acc3[2][4][4] = {};

    load_stage(0, 0); CP_COMMIT();
    load_stage(1, 1); CP_COMMIT();
    load_stage(2, 2); CP_COMMIT();

    const int NK = H / 32;   // 32
    for (int kt = 0; kt < NK; kt++) {
        CP_WAIT2();
        __syncthreads();
        if (kt + 3 < NK) load_stage(kt + 3, (kt + 3) & 3);
        CP_COMMIT();

        uint32_t stb = sb0 + (uint32_t)(kt & 3) * STG1B;
#pragma unroll
        for (int ks = 0; ks < 2; ks++) {
            uint32_t kx = ks * 32;                // XOR offset
            uint32_t a[2][4], f1[2][4], f3[2][4];
            ldsm4(a[0],  stb + (aOf[0]  ^ kx));
            ldsm4(a[1],  stb + (aOf[1]  ^ kx));
            ldsm4(f1[0], stb + (b1Of[0] ^ kx));
            ldsm4(f1[1], stb + (b1Of[1] ^ kx));
            ldsm4(f3[0], stb + (b3Of[0] ^ kx));
            ldsm4(f3[1], stb + (b3Of[1] ^ kx));
#pragma unroll
            for (int nt = 0; nt < 4; nt++) {
                int p = nt >> 1, s = (nt & 1) * 2;
#pragma unroll
                for (int mt = 0; mt < 2; mt++) {
                    mma16(acc1[mt][nt], a[mt], f1[p][s], f1[p][s + 1]);
                    mma16(acc3[mt][nt], a[mt], f3[p][s], f3[p][s + 1]);
                }
            }
        }
    }

    // epilogue: SwiGLU -> g_hh fp16
#pragma unroll
    for (int mt = 0; mt < 2; mt++) {
#pragma unroll
        for (int hf = 0; hf < 2; hf++) {
            int m = m0 + wM * 32 + mt * 16 + q + hf * 8;
            if (m >= count) continue;
            __half* hrow = g_hh + (size_t)(off + m) * F + n0 + wN * 32;
#pragma unroll
            for (int nt = 0; nt < 4; nt++) {
                float g0 = acc1[mt][nt][hf * 2 + 0];
                float g1 = acc1[mt][nt][hf * 2 + 1];
                float u0 = acc3[mt][nt][hf * 2 + 0];
                float u1 = acc3[mt][nt][hf * 2 + 1];
                float h0 = (g0 / (1.f + expf(-g0))) * u0;
                float h1 = (g1 / (1.f + expf(-g1))) * u1;
                *(__half2*)(hrow + nt * 8 + 2 * tq) = __floats2half2_rn(h0, h1);
            }
        }
    }
}

// ---------------------------------------------------------------------------
// 2. gemm2 (fp16 m16n8k16 + ldmatrix): y = c * (h @ W2^T), fp16 output
//    CTA 64x256, warps 2Mx4N (warp 32x64): 6 ldsm per 16 mma (was 4 per 8)
// ---------------------------------------------------------------------------
__global__ __launch_bounds__(256, 2) void gemm2_tc() {
    int e     = blockIdx.z;
    int off   = e * T;
    int count = g_counts[e];
    int m0    = blockIdx.x * 64;
    if (m0 >= count) return;
    int n0 = blockIdx.y * 256;

    extern __shared__ __half smh[];

    int tid = threadIdx.x, wid = tid >> 5, lane = tid & 31;
    int q = lane >> 2, tq = lane & 3;
    int wM = wid & 1, wN = wid >> 1;     // wN in 0..3, 64 cols each

    const __half* w2e = g_w2h + ((size_t)e * H + n0) * F;
    int cm1 = count - 1;

    uint32_t sb0 = smem_u32(smh);
    int lrow = tid >> 2, lseg = tid & 3;
    uint32_t wdstA = SWB64((uint32_t)(lrow * 64 + lseg * 16));
    uint32_t wdstB[4];
#pragma unroll
    for (int r = 0; r < 4; r++)
        wdstB[r] = SWB64((uint32_t)((r * 64 + lrow) * 64 + lseg * 16));
    int arow = off + min(m0 + lrow, cm1);

    uint32_t aOf[2], bOf[4];
#pragma unroll
    for (int mt = 0; mt < 2; mt++) aOf[mt] = a_off64(wM * 32 + mt * 16, lane);
#pragma unroll
    for (int p = 0; p < 4; p++) bOf[p] = 4096 + b_off64(wN * 64 + p * 16, lane);

    auto load_stage = [&](int kt, int buf) {
        uint32_t sb = sb0 + (uint32_t)buf * STG2B;
        int kf = kt * 32 + lseg * 8;
        cp_async16(sb + wdstA, g_hh + (size_t)arow * F + kf);
#pragma unroll
        for (int r = 0; r < 4; r++)
            cp_async16(sb + 4096 + wdstB[r],
                       w2e + (size_t)(r * 64 + lrow) * F + kf);
    };

    float acc[2][8][4] = {};

    load_stage(0, 0); CP_COMMIT();
    load_stage(1, 1); CP_COMMIT();
    load_stage(2, 2); CP_COMMIT();

    const int NK = F / 32;   // 16
    for (int kt = 0; kt < NK; kt++) {
        CP_WAIT2();
        __syncthreads();
        if (kt + 3 < NK) load_stage(kt + 3, (kt + 3) & 3);
        CP_COMMIT();

        uint32_t stb = sb0 + (uint32_t)(kt & 3) * STG2B;
#pragma unroll
        for (int ks = 0; ks < 2; ks++) {
            uint32_t kx = ks * 32;                // XOR offset
            uint32_t a[2][4], fb[4][4];
            ldsm4(a[0],  stb + (aOf[0] ^ kx));
            ldsm4(a[1],  stb + (aOf[1] ^ kx));
#pragma unroll
            for (int p = 0; p < 4; p++)
                ldsm4(fb[p], stb + (bOf[p] ^ kx));
#pragma unroll
            for (int nt = 0; nt < 8; nt++) {
                int p = nt >> 1, s = (nt & 1) * 2;
#pragma unroll
                for (int mt = 0; mt < 2; mt++)
                    mma16(acc[mt][nt], a[mt], fb[p][s], fb[p][s + 1]);
            }
        }
    }

    // epilogue: scale by combine weight, store g_yh fp16
#pragma unroll
    for (int mt = 0; mt < 2; mt++) {
#pragma unroll
        for (int hf = 0; hf < 2; hf++) {
            int m = m0 + wM * 32 + mt * 16 + q + hf * 8;
            if (m >= count) continue;
            float cw = g_slot_w[off + m];
            __half* yrow = g_yh + (size_t)(off + m) * H + n0 + wN * 64;
#pragma unroll
            for (int nt = 0; nt < 8; nt++) {
                float o0 = cw * acc[mt][nt][hf * 2 + 0];
                float o1 = cw * acc[mt][nt][hf * 2 + 1];
                *(__half2*)(yrow + nt * 8 + 2 * tq) = __floats2half2_rn(o0, o1);
            }
        }
    }
}

// ---------------------------------------------------------------------------
// 3. combine: out[t] = sum of the token's K slot rows (fixed order, fp32 acc)
//    Also re-zeroes g_counts for the next graph replay (counts are dead here).
// ---------------------------------------------------------------------------
__global__ void combine_kernel(float* __restrict__ out) {
    int t = blockIdx.x;
    if (t == 0 && threadIdx.x < E) g_counts[threadIdx.x] = 0;
    const __half* y0 = g_yh + (size_t)g_token_slot[t * K + 0] * H;
    const __half* y1 = g_yh + (size_t)g_token_slot[t * K + 1] * H;
    const __half* y2 = g_yh + (size_t)g_token_slot[t * K + 2] * H;
    const __half* y3 = g_yh + (size_t)g_token_slot[t * K + 3] * H;
    float* orow = out + (size_t)t * H;
    for (int c = threadIdx.x * 4; c < H; c += blockDim.x * 4) {
        uint2 a = *(const uint2*)(y0 + c), b = *(const uint2*)(y1 + c);
        uint2 cc = *(const uint2*)(y2 + c), d = *(const uint2*)(y3 + c);
        const __half2* ah = (const __half2*)&a;
        const __half2* bh = (const __half2*)&b;
        const __half2* ch = (const __half2*)&cc;
        const __half2* dh = (const __half2*)&d;
        float4 v;
        v.x = __low2float(ah[0])  + __low2float(bh[0])  + __low2float(ch[0])  + __low2float(dh[0]);
        v.y = __high2float(ah[0]) + __high2float(bh[0]) + __high2float(ch[0]) + __high2float(dh[0]);
        v.z = __low2float(ah[1])  + __low2float(bh[1])  + __low2float(ch[1])  + __low2float(dh[1]);
        v.w = __high2float(ah[1]) + __high2float(bh[1]) + __high2float(ch[1]) + __high2float(dh[1]);
        *(float4*)(orow + c) = v;
    }
}

// ---------------------------------------------------------------------------
extern "C" void kernel_launch(void* const* d_in, const int* in_sizes, int n_in,
                              void* d_out, int out_size) {
    const float* x    = (const float*)d_in[0];
    const float* gw   = (const float*)d_in[1];
    const float* bias = (const float*)d_in[2];
    const float* w1   = (const float*)d_in[3];
    const float* w3   = (const float*)d_in[4];
    const float* w2   = (const float*)d_in[5];
    float* out = (float*)d_out;

    const int SM1 = 4 * STG1B;   // 81920 B
    const int SM2 = 4 * STG2B;   // 81920 B
    cudaFuncSetAttribute(gemm1_tc, cudaFuncAttributeMaxDynamicSharedMemorySize, SM1);
    cudaFuncSetAttribute(gemm2_tc, cudaFuncAttributeMaxDynamicSharedMemorySize, SM2);

    prep_router_kernel<<<RB + PB, 256>>>(x, gw, bias, (const float4*)w1,
                                         (const float4*)w3, (const float4*)w2);

    gemm1_tc<<<dim3(T / 64, F / 128, E), 256, SM1>>>();
    gemm2_tc<<<dim3(T / 64, H / 256, E), 256, SM2>>>();

    combine_kernel<<<T, 256>>>(out);
}